// round 14
// baseline (speedup 1.0000x reference)
#include <cuda_runtime.h>
#include <cuda_bf16.h>
#include <math.h>
#include <stdint.h>

#define NN 8192
#define HH 128
#define H3 384
#define EPSF 1e-6f
#define PMF 0.9999f
#define PADU 68
#define GSMEM (384 * PADU * 4)

// ----------------------------- fp32 scratch -----------------------------
__device__ float g_Yq[NN*HH];
__device__ float g_Yup1[NN*HH], g_Yup2[NN*HH], g_Yup3[NN*HH];
__device__ float g_Yuf1[NN*HH], g_Yuf2[NN*HH], g_Yuf3[NN*HH];
__device__ float g_Ywc1[NN*HH], g_Ywc2[NN*HH], g_Ywc3[NN*HH];
__device__ float g_h1p[NN*HH], g_h1s[NN*HH], g_h1e[NN*HH];
__device__ float g_P1[NN*HH], g_P2[NN*HH], g_E3[NN*HH];
__device__ float g_Z1[NN*H3], g_Z2[NN*H3], g_Z3[NN*H3];
// per-node scalars
__device__ float g_y2p[NN], g_y2s[NN], g_lam1[NN], g_lam2[NN];
__device__ float g_nh1[NN], g_nh2[NN];
// bf16 hi/lo packed
__device__ uint32_t g_xh[NN*64],  g_xl[NN*64];
__device__ uint32_t g_l1h[NN*64], g_l1l[NN*64];
__device__ uint32_t g_l2h[NN*64], g_l2l[NN*64];
__device__ uint32_t g_h3h[NN*64], g_h3l[NN*64];
__device__ uint32_t g_lc1h[NN*64], g_lc1l[NN*64];
__device__ uint32_t g_lc2h[NN*64], g_lc2l[NN*64];
__device__ uint32_t g_c3h[NN*64], g_c3l[NN*64];
__device__ uint32_t g_A1h[NN*64], g_A1l[NN*64];
__device__ uint32_t g_A2h[NN*64], g_A2l[NN*64];
__device__ uint32_t g_A3h[NN*64], g_A3l[NN*64];
__device__ uint32_t g_Wqh[128*64], g_Wql[128*64];
__device__ uint32_t g_Wch[128*64], g_Wcl[128*64];
__device__ uint32_t g_Ufh[128*64], g_Ufl[128*64];
__device__ uint32_t g_Uph[128*64], g_Upl[128*64];
__device__ uint32_t g_Uih[384*64], g_Uil[384*64];

// ----------------------------- fast math -----------------------------
__device__ __forceinline__ float ftanh(float x){
  float a = fabsf(x);
  float r;
  if(a < 0.105f){
    float a2 = a*a;
    r = a*(1.f - a2*(0.33333334f - a2*0.13333334f));
  } else {
    float t = __expf(-2.f*a);
    r = __fdividef(1.f - t, 1.f + t);
  }
  return copysignf(r, x);
}
__device__ __forceinline__ float fatanh(float u){
  u = fminf(fmaxf(u, -1.f + 1e-5f), 1.f - 1e-5f);
  float a = fabsf(u);
  float r;
  if(a < 0.105f){
    float a2 = a*a;
    r = a*(1.f + a2*(0.33333334f + a2*0.2f));
  } else {
    r = 0.5f*__logf(__fdividef(1.f + a, 1.f - a));
  }
  return copysignf(r, u);
}
__device__ __forceinline__ float fsig(float x){
  return __fdividef(1.f, 1.f + __expf(-x));
}
__device__ __forceinline__ float ftan(float u){
  u = fminf(fmaxf(u, -1.47079f), 1.47079f);
  return __tanf(u);
}
__device__ __forceinline__ float safe_den(float d){
  return d >= 0.f ? fmaxf(d, EPSF) : fminf(d, -EPSF);
}

// ----------------------------- warp helpers -----------------------------
__device__ __forceinline__ float wred(float s){
  #pragma unroll
  for(int o=16;o;o>>=1) s += __shfl_xor_sync(0xffffffffu, s, o);
  return s;
}
template<int R> __device__ __forceinline__ float wdot(const float* a, const float* b){
  float s=0.f;
  #pragma unroll
  for(int i=0;i<R;i++) s += a[i]*b[i];
  return wred(s);
}
__device__ __forceinline__ void ld4(float* v, const float* p){
  float4 t = *(const float4*)p; v[0]=t.x; v[1]=t.y; v[2]=t.z; v[3]=t.w;
}
__device__ __forceinline__ void st4(float* p, const float* v){
  *(float4*)p = make_float4(v[0],v[1],v[2],v[3]);
}

__device__ __forceinline__ float pwmulp_k(const float* w, const float* x, float nx, float* o){
  float wx[4];
  #pragma unroll
  for(int i=0;i<4;i++) wx[i] = w[i]*x[i];
  float nwx = sqrtf(wdot<4>(wx,wx) + 1e-15f);
  float m = fminf(ftanh(__fdividef(nwx,nx)*fatanh(nx)), PMF);
  float s = __fdividef(m, nwx);
  #pragma unroll
  for(int i=0;i<4;i++) o[i] = wx[i]*s;
  return m;
}
__device__ __forceinline__ float pwmuls_k(const float* w, const float* x, float nx, float* o){
  float wx[4];
  #pragma unroll
  for(int i=0;i<4;i++) wx[i] = w[i]*x[i];
  float nwx = sqrtf(wdot<4>(wx,wx) + 1e-15f);
  float m = ftan(__fdividef(nwx,nx)*atanf(nx));
  float s = __fdividef(m, nwx);
  #pragma unroll
  for(int i=0;i<4;i++) o[i] = wx[i]*s;
  return m;
}
__device__ __forceinline__ void softmax8(float* s){
  float m = s[0];
  #pragma unroll
  for(int k=1;k<8;k++) m = fmaxf(m, s[k]);
  float sum = 0.f;
  #pragma unroll
  for(int k=0;k<8;k++){ s[k] = __expf(s[k]-m); sum += s[k]; }
  float inv = __fdividef(1.f, sum);
  #pragma unroll
  for(int k=0;k<8;k++) s[k] *= inv;
}

// ----------------------------- bf16 packing -----------------------------
__device__ __forceinline__ uint32_t pack_bf2(float f0, float f1){
  __nv_bfloat16 b0 = __float2bfloat16_rn(f0);
  __nv_bfloat16 b1 = __float2bfloat16_rn(f1);
  return ((uint32_t)__bfloat16_as_ushort(b1)<<16) | (uint32_t)__bfloat16_as_ushort(b0);
}
__device__ __forceinline__ void split_bf2(float f0, float f1, uint32_t& hi, uint32_t& lo){
  __nv_bfloat16 b0 = __float2bfloat16_rn(f0);
  __nv_bfloat16 b1 = __float2bfloat16_rn(f1);
  hi = ((uint32_t)__bfloat16_as_ushort(b1)<<16) | (uint32_t)__bfloat16_as_ushort(b0);
  lo = pack_bf2(f0 - __bfloat162float(b0), f1 - __bfloat162float(b1));
}
__device__ __forceinline__ void pack_store(uint32_t* dh, uint32_t* dl, int idx, const float* v){
  uint32_t h0,l0,h1,l1;
  split_bf2(v[0],v[1],h0,l0);
  split_bf2(v[2],v[3],h1,l1);
  *(uint2*)(dh+idx) = make_uint2(h0,h1);
  *(uint2*)(dl+idx) = make_uint2(l0,l1);
}

// ----------------------------- GEMM (pre-packed bf16 3-term, ldmatrix) -----------------------------
__device__ __forceinline__ void mma16(float* d, const uint32_t* a, const uint32_t* b){
  asm volatile("mma.sync.aligned.m16n8k16.row.col.f32.bf16.bf16.f32 "
    "{%0,%1,%2,%3},{%4,%5,%6,%7},{%8,%9},{%0,%1,%2,%3};"
    : "+f"(d[0]),"+f"(d[1]),"+f"(d[2]),"+f"(d[3])
    : "r"(a[0]),"r"(a[1]),"r"(a[2]),"r"(a[3]),"r"(b[0]),"r"(b[1]));
}
__device__ __forceinline__ void ldsm4(uint32_t& r0, uint32_t& r1, uint32_t& r2, uint32_t& r3, uint32_t addr){
  asm volatile("ldmatrix.sync.aligned.m8n8.x4.shared.b16 {%0,%1,%2,%3}, [%4];"
    : "=r"(r0),"=r"(r1),"=r"(r2),"=r"(r3) : "r"(addr));
}

__device__ __forceinline__ void gemm_pk(const uint32_t* __restrict__ AhG, const uint32_t* __restrict__ AlG,
                                        const uint32_t* __restrict__ BhG, const uint32_t* __restrict__ BlG,
                                        const float* __restrict__ bias, float* __restrict__ C, int HO){
  extern __shared__ uint32_t sh[];
  uint32_t* Ah = sh;
  uint32_t* Al = sh + 64*PADU;
  uint32_t* Bh = sh + 128*PADU;
  uint32_t* Bl = sh + 256*PADU;
  const int m0 = blockIdx.x*64;
  const int n0 = blockIdx.y*128;
  const int t = threadIdx.x;
  const int lane = t & 31, w = t >> 5;
  const int wm = w >> 2, wn = w & 3;
  const int gid = lane >> 2, tig = lane & 3;

  #pragma unroll
  for(int i=0;i<4;i++){
    int p = t + i*256; int r = p>>4, c = (p&15)*4;
    *(uint4*)(Ah + r*PADU + c) = *(const uint4*)(AhG + (m0+r)*64 + c);
    *(uint4*)(Al + r*PADU + c) = *(const uint4*)(AlG + (m0+r)*64 + c);
  }
  #pragma unroll
  for(int i=0;i<8;i++){
    int p = t + i*256; int r = p>>4, c = (p&15)*4;
    *(uint4*)(Bh + r*PADU + c) = *(const uint4*)(BhG + (n0+r)*64 + c);
    *(uint4*)(Bl + r*PADU + c) = *(const uint4*)(BlG + (n0+r)*64 + c);
  }
  __syncthreads();

  uint32_t shbase = (uint32_t)__cvta_generic_to_shared(sh);
  int rowA = wm*32 + (lane & 15);
  int colA = ((lane >> 4) & 1) * 4;
  uint32_t aAh0 = shbase + (uint32_t)((rowA*PADU + colA) * 4);
  uint32_t aAh1 = aAh0 + 16u*PADU*4u;
  uint32_t aAl0 = aAh0 + 64u*PADU*4u;
  uint32_t aAl1 = aAh1 + 64u*PADU*4u;
  int rowB = wn*32 + ((lane >> 4) & 1) * 8 + (lane & 7);
  int colB = ((lane >> 3) & 1) * 4;
  uint32_t aBh0 = shbase + (uint32_t)((128*PADU + rowB*PADU + colB) * 4);
  uint32_t aBh1 = aBh0 + 16u*PADU*4u;
  uint32_t aBl0 = aBh0 + 128u*PADU*4u;
  uint32_t aBl1 = aBh1 + 128u*PADU*4u;

  float acc[2][4][4];
  #pragma unroll
  for(int mt=0;mt<2;mt++)
    #pragma unroll
    for(int nt=0;nt<4;nt++)
      #pragma unroll
      for(int i=0;i<4;i++) acc[mt][nt][i]=0.f;

  #pragma unroll
  for(int s=0;s<8;s++){
    uint32_t ko = (uint32_t)(s*8*4);
    uint32_t ah[2][4], al[2][4], bh[4][2], bl[4][2];
    ldsm4(ah[0][0], ah[0][1], ah[0][2], ah[0][3], aAh0 + ko);
    ldsm4(ah[1][0], ah[1][1], ah[1][2], ah[1][3], aAh1 + ko);
    ldsm4(al[0][0], al[0][1], al[0][2], al[0][3], aAl0 + ko);
    ldsm4(al[1][0], al[1][1], al[1][2], al[1][3], aAl1 + ko);
    ldsm4(bh[0][0], bh[0][1], bh[1][0], bh[1][1], aBh0 + ko);
    ldsm4(bh[2][0], bh[2][1], bh[3][0], bh[3][1], aBh1 + ko);
    ldsm4(bl[0][0], bl[0][1], bl[1][0], bl[1][1], aBl0 + ko);
    ldsm4(bl[2][0], bl[2][1], bl[3][0], bl[3][1], aBl1 + ko);
    #pragma unroll
    for(int mt=0;mt<2;mt++)
      #pragma unroll
      for(int nt=0;nt<4;nt++){
        mma16(acc[mt][nt], al[mt], bh[nt]);
        mma16(acc[mt][nt], ah[mt], bl[nt]);
        mma16(acc[mt][nt], ah[mt], bh[nt]);
      }
  }

  #pragma unroll
  for(int mt=0;mt<2;mt++){
    int r = m0 + wm*32 + mt*16 + gid;
    #pragma unroll
    for(int nt=0;nt<4;nt++){
      int c = n0 + wn*32 + nt*8 + tig*2;
      float b0 = bias[c], b1 = bias[c+1];
      *(float2*)(C + r*HO + c)     = make_float2(acc[mt][nt][0]+b0, acc[mt][nt][1]+b1);
      *(float2*)(C + (r+8)*HO + c) = make_float2(acc[mt][nt][2]+b0, acc[mt][nt][3]+b1);
    }
  }
}

__global__ void __launch_bounds__(256) k_gemm1(const float* __restrict__ bq, const float* __restrict__ bc,
                                               const float* __restrict__ bf, const float* __restrict__ bp){
  const uint32_t *Ah,*Al,*Bh,*Bl; const float* B; float* C;
  switch(blockIdx.z){
    case 0: Ah=g_xh;  Al=g_xl;  Bh=g_Wqh; Bl=g_Wql; B=bq; C=g_Yq;   break;
    case 1: Ah=g_l1h; Al=g_l1l; Bh=g_Uph; Bl=g_Upl; B=bp; C=g_Yup1; break;
    case 2: Ah=g_l2h; Al=g_l2l; Bh=g_Uph; Bl=g_Upl; B=bp; C=g_Yup2; break;
    case 3: Ah=g_h3h; Al=g_h3l; Bh=g_Uph; Bl=g_Upl; B=bp; C=g_Yup3; break;
    case 4: Ah=g_l1h; Al=g_l1l; Bh=g_Ufh; Bl=g_Ufl; B=bf; C=g_Yuf1; break;
    case 5: Ah=g_l2h; Al=g_l2l; Bh=g_Ufh; Bl=g_Ufl; B=bf; C=g_Yuf2; break;
    case 6: Ah=g_h3h; Al=g_h3l; Bh=g_Ufh; Bl=g_Ufl; B=bf; C=g_Yuf3; break;
    case 7: Ah=g_lc1h;Al=g_lc1l;Bh=g_Wch; Bl=g_Wcl; B=bc; C=g_Ywc1; break;
    case 8: Ah=g_lc2h;Al=g_lc2l;Bh=g_Wch; Bl=g_Wcl; B=bc; C=g_Ywc2; break;
    default:Ah=g_c3h; Al=g_c3l; Bh=g_Wch; Bl=g_Wcl; B=bc; C=g_Ywc3; break;
  }
  gemm_pk(Ah, Al, Bh, Bl, B, C, 128);
}

__global__ void __launch_bounds__(256) k_gemm2(const float* __restrict__ bi){
  const uint32_t *Ah,*Al; float* C;
  switch(blockIdx.z){
    case 0: Ah=g_A1h; Al=g_A1l; C=g_Z1; break;
    case 1: Ah=g_A2h; Al=g_A2l; C=g_Z2; break;
    default:Ah=g_A3h; Al=g_A3l; C=g_Z3; break;
  }
  gemm_pk(Ah, Al, g_Uih, g_Uil, bi, C, 384);
}

// ----------------------------- prep -----------------------------
__global__ void k_prep(const float* __restrict__ h1, const float* __restrict__ h2,
                       const float* __restrict__ c1, const float* __restrict__ c2,
                       const float* __restrict__ x,  const float* __restrict__ h3,
                       const float* __restrict__ c3,
                       const float* __restrict__ Wq, const float* __restrict__ Wc,
                       const float* __restrict__ Uf, const float* __restrict__ Up,
                       const float* __restrict__ Ui){
  if(blockIdx.x >= NN/8){
    int i = (blockIdx.x - NN/8)*256 + threadIdx.x;
    const float* src; uint32_t *dh, *dl; int off;
    if(i < 8192){ src=Wq; dh=g_Wqh; dl=g_Wql; off=i; }
    else if(i < 16384){ src=Wc; dh=g_Wch; dl=g_Wcl; off=i-8192; }
    else if(i < 24576){ src=Uf; dh=g_Ufh; dl=g_Ufl; off=i-16384; }
    else if(i < 32768){ src=Up; dh=g_Uph; dl=g_Upl; off=i-24576; }
    else if(i < 57344){ src=Ui; dh=g_Uih; dl=g_Uil; off=i-32768; }
    else return;
    float2 v = *(const float2*)(src + off*2);
    uint32_t hi, lo; split_bf2(v.x, v.y, hi, lo);
    dh[off]=hi; dl[off]=lo;
    return;
  }
  int nd = (blockIdx.x*blockDim.x + threadIdx.x) >> 5;
  int l = threadIdx.x & 31;
  int b = nd*128 + l*4;
  int bi = nd*64 + l*2;
  float v[4], w[4];
  ld4(v, h1+b);
  float nr = sqrtf(wdot<4>(v,v) + 1e-15f);
  float s = __fdividef(fatanh(nr), nr);
  #pragma unroll
  for(int i=0;i<4;i++) w[i]=v[i]*s;
  pack_store(g_l1h,g_l1l,bi,w);
  if(l==0) g_nh1[nd] = nr;
  ld4(v, h2+b);
  nr = sqrtf(wdot<4>(v,v) + 1e-15f);
  s = __fdividef(atanf(nr), nr);
  #pragma unroll
  for(int i=0;i<4;i++) w[i]=v[i]*s;
  pack_store(g_l2h,g_l2l,bi,w);
  if(l==0) g_nh2[nd] = nr;
  ld4(v, c1+b);
  nr = sqrtf(wdot<4>(v,v) + 1e-15f);
  s = __fdividef(fatanh(nr), nr);
  #pragma unroll
  for(int i=0;i<4;i++) w[i]=v[i]*s;
  pack_store(g_lc1h,g_lc1l,bi,w);
  ld4(v, c2+b);
  nr = sqrtf(wdot<4>(v,v) + 1e-15f);
  s = __fdividef(atanf(nr), nr);
  #pragma unroll
  for(int i=0;i<4;i++) w[i]=v[i]*s;
  pack_store(g_lc2h,g_lc2l,bi,w);
  ld4(v, x+b);  pack_store(g_xh, g_xl, bi, v);
  ld4(v, h3+b); pack_store(g_h3h,g_h3l,bi, v);
  ld4(v, c3+b); pack_store(g_c3h,g_c3l,bi, v);
}

// ----------------------------- per-node elementwise (split 2-way, reg-capped) -----------------------------
__global__ void __launch_bounds__(256, 4) k_node(const float* __restrict__ h1, const float* __restrict__ h2,
                       const float* __restrict__ h3, const float* __restrict__ c1,
                       const float* __restrict__ c2, const float* __restrict__ c3,
                       const float* __restrict__ del_t, const float* __restrict__ dptr){
  int nd = (blockIdx.x*blockDim.x + threadIdx.x) >> 5;
  if(nd >= NN) return;
  int l = threadIdx.x & 31;
  int b = nd*128 + l*4;

  if(blockIdx.y == 0){
    float s1[4];
    {
      ld4(s1, g_Yup1+b);
      float nt = sqrtf(wdot<4>(s1,s1)+1e-15f);
      float me = fminf(ftanh(nt), PMF);
      float sc = __fdividef(me, nt);
      #pragma unroll
      for(int i=0;i<4;i++) s1[i] = fsig(s1[i]*sc);
      float ns = sqrtf(wdot<4>(s1,s1)+1e-15f);
      float sl = __fdividef(fatanh(ns), ns);
      #pragma unroll
      for(int i=0;i<4;i++) s1[i] *= sl;
    }
    float s2[4];
    {
      ld4(s2, g_Yup2+b);
      float nt = sqrtf(wdot<4>(s2,s2)+1e-15f);
      float me = ftan(nt);
      float sc = __fdividef(me, nt);
      #pragma unroll
      for(int i=0;i<4;i++) s2[i] = fsig(s2[i]*sc);
      float ns = sqrtf(wdot<4>(s2,s2)+1e-15f);
      float sl = __fdividef(atanf(ns), ns);
      #pragma unroll
      for(int i=0;i<4;i++) s2[i] *= sl;
    }
    float s3[4]; ld4(s3, g_Yup3+b);
    #pragma unroll
    for(int i=0;i<4;i++) s3[i] = fsig(s3[i]);

    float h1v[4],h2v[4],h3v[4];
    ld4(h1v, h1+b); ld4(h2v, h2+b); ld4(h3v, h3+b);
    float nh1 = g_nh1[nd], nh2 = g_nh2[nd];
    float nh3 = sqrtf(wdot<4>(h3v,h3v)+1e-15f);

    float ht1p[4], ht2p[4], ht3p[4], tmp[4];
    float m1p = pwmulp_k(s1, h1v, nh1, ht1p);
    float m2p, m3p;
    {
      float mm = fminf(ftanh(atanf(nh2)), PMF);
      float sc = __fdividef(mm, nh2);
      #pragma unroll
      for(int i=0;i<4;i++) tmp[i] = h2v[i]*sc;
      m2p = pwmulp_k(s2, tmp, mm, ht2p);
    }
    {
      float mm = fminf(ftanh(nh3), PMF);
      float sc = __fdividef(mm, nh3);
      #pragma unroll
      for(int i=0;i<4;i++) tmp[i] = h3v[i]*sc;
      m3p = pwmulp_k(s3, tmp, mm, ht3p);
    }
    {
      float la = __fdividef(2.f, 1.f-m1p*m1p);
      float lb = __fdividef(2.f, 1.f-m2p*m2p);
      float lc = __fdividef(2.f, 1.f-m3p*m3p);
      float den = fmaxf(fabsf(la+lb+lc-3.f), EPSF);
      float num[4];
      #pragma unroll
      for(int i=0;i<4;i++) num[i] = la*ht1p[i]+lb*ht2p[i]+lc*ht3p[i];
      float nnum = sqrtf(wdot<4>(num,num)+1e-15f);
      float nn = __fdividef(nnum, den);
      float m = fminf(ftanh(0.5f*fatanh(nn)), PMF);
      float sc = __fdividef(3.f*m, nnum);
      #pragma unroll
      for(int i=0;i<4;i++) num[i] *= sc;
      st4(g_h1p+b, num);
      if(l==0) g_y2p[nd] = 9.f*m*m;
    }

    float ht1s[4], ht2s[4], ht3s[4];
    float m2s;
    {
      float nl1 = fatanh(nh1);
      float mm = ftan(nl1);
      float sc = __fdividef(mm, nh1);
      #pragma unroll
      for(int i=0;i<4;i++) tmp[i] = h1v[i]*sc;
      float m1s = pwmulp_k(s1, tmp, mm, ht1s);
      m2s = pwmuls_k(s2, h2v, nh2, ht2s);
      float mm3 = ftan(nh3);
      float sc3 = __fdividef(mm3, nh3);
      #pragma unroll
      for(int i=0;i<4;i++) tmp[i] = h3v[i]*sc3;
      float m3s = pwmuls_k(s3, tmp, mm3, ht3s);
      float la = __fdividef(2.f, 1.f-m1s*m1s);
      float lb = __fdividef(2.f, 1.f-m2s*m2s);
      float lc = __fdividef(2.f, 1.f-m3s*m3s);
      float den = fmaxf(fabsf(la+lb+lc-3.f), EPSF);
      float num[4];
      #pragma unroll
      for(int i=0;i<4;i++) num[i] = la*ht1s[i]+lb*ht2s[i]+lc*ht3s[i];
      float nnum = sqrtf(wdot<4>(num,num)+1e-15f);
      float nn = __fdividef(nnum, den);
      float m = fminf(ftanh(0.5f*fatanh(nn)), PMF);
      float sc2 = __fdividef(3.f*m, nnum);
      #pragma unroll
      for(int i=0;i<4;i++) num[i] *= sc2;
      st4(g_h1s+b, num);
      if(l==0) g_y2s[nd] = 9.f*m*m;
    }

    {
      float e1s = __fdividef(fatanh(m1p), m1p);
      float e2s = __fdividef(atanf(m2s), m2s);
      float he[4];
      #pragma unroll
      for(int i=0;i<4;i++) he[i] = ht1p[i]*e1s + ht2s[i]*e2s + s3[i]*h3v[i];
      st4(g_h1e+b, he);
    }
  } else {
    float g = __fdividef(dptr[0], del_t[nd] + 1.f);
    float nx2 = sqrtf(g*g + 1e-15f);
    float ax2 = fatanh(nx2);
    float sx2 = atanf(nx2);

    // Poincare cell
    {
      float c1v[4]; ld4(c1v, c1+b);
      float cw[4]; ld4(cw, g_Ywc1+b);
      float nw = sqrtf(wdot<4>(cw,cw)+1e-15f);
      {
        float sc = __fdividef(fatanh(fminf(ftanh(nw),PMF)), nw);
        #pragma unroll
        for(int i=0;i<4;i++) cw[i] = ftanh(cw[i]*sc);
      }
      float nck = sqrtf(wdot<4>(cw,cw)+1e-15f);
      float mk = fminf(ftanh(nck), PMF);
      {
        float sc = __fdividef(mk, nck);
        #pragma unroll
        for(int i=0;i<4;i++) cw[i] *= sc;
      }
      float x2 = mk*mk;
      float y2 = wdot<4>(c1v,c1v);
      float xys = 0.f;
      #pragma unroll
      for(int i=0;i<4;i++) xys -= cw[i]*c1v[i];
      float xy = wred(xys);
      float cx = 1.f+2.f*xy+y2, cy = 1.f-x2;
      float idn = __fdividef(1.f, safe_den(1.f+2.f*xy+x2*y2));
      float t1[4];
      #pragma unroll
      for(int i=0;i<4;i++) t1[i] = (cx*(-cw[i]) + cy*c1v[i])*idn;
      float n2t1 = fmaxf((cx*cx*x2 + 2.f*cx*cy*xy + cy*cy*y2)*idn*idn, 0.f);
      if(n2t1 > PMF*PMF){
        float sc = PMF*rsqrtf(n2t1);
        #pragma unroll
        for(int i=0;i<4;i++) t1[i] *= sc;
        n2t1 = PMF*PMF;
      }
      float m2 = fminf(ftanh(__fdividef(g*mk, nx2)*ax2), PMF);
      float t2s = __fdividef(m2, mk);
      float xys2 = 0.f;
      #pragma unroll
      for(int i=0;i<4;i++) xys2 += t1[i]*cw[i]*t2s;
      float xy2 = wred(xys2);
      x2 = n2t1; y2 = m2*m2;
      cx = 1.f+2.f*xy2+y2; cy = 1.f-x2;
      idn = __fdividef(1.f, safe_den(1.f+2.f*xy2+x2*y2));
      float ck[4];
      #pragma unroll
      for(int i=0;i<4;i++) ck[i] = (cx*t1[i] + cy*cw[i]*t2s)*idn;
      float n2ck = fmaxf((cx*cx*x2 + 2.f*cx*cy*xy2 + cy*cy*y2)*idn*idn, 0.f);
      float nckt = sqrtf(n2ck + 1e-15f);
      if(nckt > PMF){
        float sc = __fdividef(PMF, nckt);
        #pragma unroll
        for(int i=0;i<4;i++) ck[i] *= sc;
        nckt = PMF;
      }
      float fp[4]; ld4(fp, g_Yuf1+b);
      float nf = sqrtf(wdot<4>(fp,fp)+1e-15f);
      float scf = __fdividef(fatanh(fminf(ftanh(nf),PMF)), nf);
      #pragma unroll
      for(int i=0;i<4;i++) fp[i] = fsig(fp[i]*scf);
      float P1[4];
      float mP1 = pwmulp_k(fp, ck, nckt, P1);
      st4(g_P1+b, P1);
      if(l==0) g_lam1[nd] = __fdividef(2.f, 1.f-mP1*mP1);
    }

    // Sphere cell
    {
      float c2v[4]; ld4(c2v, c2+b);
      float cw[4]; ld4(cw, g_Ywc2+b);
      float nw = sqrtf(wdot<4>(cw,cw)+1e-15f);
      {
        float sc = __fdividef(atanf(ftan(nw)), nw);
        #pragma unroll
        for(int i=0;i<4;i++) cw[i] = ftanh(cw[i]*sc);
      }
      float nck = sqrtf(wdot<4>(cw,cw)+1e-15f);
      float mk = ftan(nck);
      {
        float sc = __fdividef(mk, nck);
        #pragma unroll
        for(int i=0;i<4;i++) cw[i] *= sc;
      }
      float x2 = mk*mk;
      float y2 = wdot<4>(c2v,c2v);
      float xys = 0.f;
      #pragma unroll
      for(int i=0;i<4;i++) xys -= cw[i]*c2v[i];
      float xy = wred(xys);
      float cx = 1.f-2.f*xy-y2, cy = 1.f+x2;
      float idn = __fdividef(1.f, safe_den(1.f-2.f*xy+x2*y2));
      float t1[4];
      #pragma unroll
      for(int i=0;i<4;i++) t1[i] = (cx*(-cw[i]) + cy*c2v[i])*idn;
      float n2t1 = fmaxf((cx*cx*x2 + 2.f*cx*cy*xy + cy*cy*y2)*idn*idn, 0.f);
      float m2 = ftan(__fdividef(g*mk, nx2)*sx2);
      float t2s = __fdividef(m2, mk);
      float xys2 = 0.f;
      #pragma unroll
      for(int i=0;i<4;i++) xys2 += t1[i]*cw[i]*t2s;
      float xy2 = wred(xys2);
      x2 = n2t1; y2 = m2*m2;
      cx = 1.f-2.f*xy2-y2; cy = 1.f+x2;
      idn = __fdividef(1.f, safe_den(1.f-2.f*xy2+x2*y2));
      float ck[4];
      #pragma unroll
      for(int i=0;i<4;i++) ck[i] = (cx*t1[i] + cy*cw[i]*t2s)*idn;
      float n2ck = fmaxf((cx*cx*x2 + 2.f*cx*cy*xy2 + cy*cy*y2)*idn*idn, 0.f);
      float nckt = sqrtf(n2ck + 1e-15f);
      float fs[4]; ld4(fs, g_Yuf2+b);
      float nf = sqrtf(wdot<4>(fs,fs)+1e-15f);
      float scf = __fdividef(atanf(ftan(nf)), nf);
      #pragma unroll
      for(int i=0;i<4;i++) fs[i] = fsig(fs[i]*scf);
      float P2[4];
      float mP2 = pwmuls_k(fs, ck, nckt, P2);
      st4(g_P2+b, P2);
      if(l==0) g_lam2[nd] = __fdividef(2.f, 1.f+mP2*mP2);
    }

    // Euclid cell
    {
      float c3v[4]; ld4(c3v, c3+b);
      float cske[4]; ld4(cske, g_Ywc3+b);
      float fe[4]; ld4(fe, g_Yuf3+b);
      float E3[4];
      #pragma unroll
      for(int i=0;i<4;i++){
        float ck = ftanh(cske[i]);
        E3[i] = fsig(fe[i])*(c3v[i] - ck + ck*g);
      }
      st4(g_E3+b, E3);
    }
  }
}

// ----------------------------- attention only -----------------------------
__global__ void __launch_bounds__(256, 4) k_attn(const int* __restrict__ nbr){
  int nd = (blockIdx.x*blockDim.x + threadIdx.x) >> 5;
  if(nd >= NN) return;
  int l = threadIdx.x & 31;
  int b = nd*128 + l*4;
  int bi = nd*64 + l*2;
  const int* nb = nbr + nd*8;
  int j8[8];
  #pragma unroll
  for(int k=0;k<8;k++) j8[k] = nb[k];

  float yq[4]; ld4(yq, g_Yq+b);
  float nq = sqrtf(wdot<4>(yq,yq) + 1e-15f);

  // ===== Section 1: Poincare attention =====
  {
    float mp = fminf(ftanh(nq), PMF);
    float x2 = mp*mp;
    float xq[4];
    float sp = __fdividef(mp, nq);
    #pragma unroll
    for(int i=0;i<4;i++) xq[i] = yq[i]*sp;
    float sc[8];
    #pragma unroll
    for(int k=0;k<8;k++){
      float hk[4]; ld4(hk, g_h1p + j8[k]*128 + l*4);
      float y2 = g_y2p[j8[k]];
      float s = 0.f;
      #pragma unroll
      for(int i=0;i<4;i++) s -= xq[i]*hk[i];
      float xy = wred(s);
      float cx = 1.f + 2.f*xy + y2;
      float cy = 1.f - x2;
      float dn = safe_den(1.f + 2.f*xy + x2*y2);
      float o2 = cx*cx*x2 + 2.f*cx*cy*xy + cy*cy*y2;
      float nr = fminf(__fdividef(sqrtf(fmaxf(o2,0.f) + 1e-15f), fabsf(dn)), PMF);
      sc[k] = -2.f*fatanh(nr);
    }
    softmax8(sc);
    float num[4] = {0,0,0,0};
    float ds = 0.f;
    #pragma unroll
    for(int k=0;k<8;k++){
      float hk[4]; ld4(hk, g_h1p + j8[k]*128 + l*4);
      float lam = __fdividef(2.f, 1.f - g_y2p[j8[k]]);
      float wk = sc[k]*lam;
      #pragma unroll
      for(int i=0;i<4;i++) num[i] += wk*hk[i];
      ds += sc[k]*(lam - 1.f);
    }
    float den = fmaxf(fabsf(ds), EPSF);
    float nnum = sqrtf(wdot<4>(num,num) + 1e-15f);
    float nn = __fdividef(nnum, den);
    float m = fminf(ftanh(0.5f*fatanh(nn)), PMF);
    float st = __fdividef(fatanh(m), nnum);
    #pragma unroll
    for(int i=0;i<4;i++) num[i] *= st;
    pack_store(g_A1h, g_A1l, bi, num);
  }

  // ===== Section 2: Sphere attention =====
  {
    float msp = ftan(nq);
    float x2 = msp*msp;
    float xq[4];
    float ss = __fdividef(msp, nq);
    #pragma unroll
    for(int i=0;i<4;i++) xq[i] = yq[i]*ss;
    float sc[8];
    #pragma unroll
    for(int k=0;k<8;k++){
      float hk[4]; ld4(hk, g_h1s + j8[k]*128 + l*4);
      float y2 = g_y2s[j8[k]];
      float s = 0.f;
      #pragma unroll
      for(int i=0;i<4;i++) s -= xq[i]*hk[i];
      float xy = wred(s);
      float cx = 1.f - 2.f*xy - y2;
      float cy = 1.f + x2;
      float dn = safe_den(1.f - 2.f*xy + x2*y2);
      float o2 = cx*cx*x2 + 2.f*cx*cy*xy + cy*cy*y2;
      float nr = __fdividef(sqrtf(fmaxf(o2,0.f) + 1e-15f), fabsf(dn));
      sc[k] = -2.f*atanf(nr);
    }
    softmax8(sc);
    float num[4] = {0,0,0,0};
    float ds = 0.f;
    #pragma unroll
    for(int k=0;k<8;k++){
      float hk[4]; ld4(hk, g_h1s + j8[k]*128 + l*4);
      float lam = __fdividef(2.f, 1.f + g_y2s[j8[k]]);
      float wk = sc[k]*lam;
      #pragma unroll
      for(int i=0;i<4;i++) num[i] += wk*hk[i];
      ds += sc[k]*(lam - 1.f);
    }
    float den = fmaxf(fabsf(ds), EPSF);
    float nnum = sqrtf(wdot<4>(num,num) + 1e-15f);
    float nn = __fdividef(nnum, den);
    float m = ftan(0.5f*atanf(nn));
    float st = __fdividef(atanf(m), nnum);
    #pragma unroll
    for(int i=0;i<4;i++) num[i] *= st;
    pack_store(g_A2h, g_A2l, bi, num);
  }

  // ===== Section 3: Euclid attention =====
  {
    const float isq = 0.08838834764831845f;
    float sc[8];
    #pragma unroll
    for(int k=0;k<8;k++){
      float hk[4]; ld4(hk, g_h1e + j8[k]*128 + l*4);
      float s = 0.f;
      #pragma unroll
      for(int i=0;i<4;i++) s += hk[i]*yq[i];
      sc[k] = wred(s)*isq;
    }
    softmax8(sc);
    float num[4] = {0,0,0,0};
    #pragma unroll
    for(int k=0;k<8;k++){
      float hk[4]; ld4(hk, g_h1e + j8[k]*128 + l*4);
      #pragma unroll
      for(int i=0;i<4;i++) num[i] += sc[k]*hk[i];
    }
    pack_store(g_A3h, g_A3l, bi, num);
  }
}

// ----------------------------- final epilogue (inlined cell reductions, reg-capped) -----------------------------
__global__ void __launch_bounds__(256, 3) k_final(const float* __restrict__ iou1, const float* __restrict__ iou2,
                        const float* __restrict__ iou3, const int* __restrict__ nbr,
                        float* __restrict__ out){
  int nd = (blockIdx.x*blockDim.x + threadIdx.x) >> 5;
  if(nd >= NN) return;
  int l = threadIdx.x & 31;
  int b = nd*128 + l*4;
  int b3 = nd*384 + l*4;
  const int* nb = nbr + nd*8;
  int j8[8];
  #pragma unroll
  for(int k=0;k<8;k++) j8[k] = nb[k];

  // ---- Poincare
  {
    // inline cell reduction -> cc, y2c
    float cc[4] = {0,0,0,0};
    float y2c;
    {
      float d1 = 0.f;
      #pragma unroll
      for(int k=0;k<8;k++){
        float pv[4]; ld4(pv, g_P1 + j8[k]*128 + l*4);
        float lam = g_lam1[j8[k]];
        #pragma unroll
        for(int i=0;i<4;i++) cc[i] += lam*pv[i];
        d1 += lam - 1.f;
      }
      float den = fmaxf(fabsf(d1), EPSF);
      float nnum = sqrtf(wdot<4>(cc,cc) + 1e-15f);
      float nn = __fdividef(nnum, den);
      float m = fminf(ftanh(0.5f*fatanh(nn)), PMF);
      float st = __fdividef(m, nnum);
      #pragma unroll
      for(int i=0;i<4;i++) cc[i] *= st;
      y2c = m*m;
    }
    float z[12], io[12];
    #pragma unroll
    for(int c=0;c<3;c++){ ld4(z+4*c, g_Z1 + b3 + 128*c); ld4(io+4*c, iou1 + b3 + 128*c); }
    float nz = sqrtf(wdot<12>(z,z)+1e-15f);
    float mz = fminf(ftanh(nz), PMF);
    {
      float sc = __fdividef(mz, nz);
      #pragma unroll
      for(int i=0;i<12;i++) z[i] *= sc;
    }
    float x2 = wdot<12>(io,io);
    float xy = wdot<12>(io,z);
    float y2 = mz*mz;
    float cx = 1.f+2.f*xy+y2, cy = 1.f-x2;
    float idn = __fdividef(1.f, safe_den(1.f+2.f*xy+x2*y2));
    float ni[12];
    #pragma unroll
    for(int i=0;i<12;i++) ni[i] = (cx*io[i] + cy*z[i])*idn;
    float n2ni = fmaxf((cx*cx*x2 + 2.f*cx*cy*xy + cy*cy*y2)*idn*idn, 0.f);
    if(n2ni > PMF*PMF){
      float sc = PMF*rsqrtf(n2ni);
      #pragma unroll
      for(int i=0;i<12;i++) ni[i] *= sc;
    }
    float ip[4], op[4], up[4];
    {
      float n0 = sqrtf(wdot<4>(ni,ni)+1e-15f);
      float s0 = __fdividef(fatanh(n0), n0);
      float n1 = sqrtf(wdot<4>(ni+4,ni+4)+1e-15f);
      float s1 = __fdividef(fatanh(n1), n1);
      float n2 = sqrtf(wdot<4>(ni+8,ni+8)+1e-15f);
      float s2 = __fdividef(fatanh(n2), n2);
      #pragma unroll
      for(int i=0;i<4;i++){
        ip[i] = fsig(ni[i]*s0);
        op[i] = fsig(ni[4+i]*s1);
        up[i] = ftanh(ni[8+i]*s2);
      }
    }
    float nup = sqrtf(wdot<4>(up,up)+1e-15f);
    float t[4];
    float mt = pwmulp_k(ip, up, nup, t);
    float xys = 0.f;
    #pragma unroll
    for(int i=0;i<4;i++) xys += t[i]*cc[i];
    float xyc = wred(xys);
    float x2c = mt*mt;
    float cxc = 1.f+2.f*xyc+y2c, cyc = 1.f-x2c;
    float idnc = __fdividef(1.f, safe_den(1.f+2.f*xyc+x2c*y2c));
    float nc[4];
    #pragma unroll
    for(int i=0;i<4;i++) nc[i] = (cxc*t[i] + cyc*cc[i])*idnc;
    float n2nc = fmaxf((cxc*cxc*x2c + 2.f*cxc*cyc*xyc + cyc*cyc*y2c)*idnc*idnc, 0.f);
    float nnc = sqrtf(n2nc + 1e-15f);
    if(nnc > PMF){
      float sc = __fdividef(PMF, nnc);
      #pragma unroll
      for(int i=0;i<4;i++) nc[i] *= sc;
      nnc = PMF;
    }
    float lt[4];
    {
      float sc = __fdividef(fatanh(nnc), nnc);
      #pragma unroll
      for(int i=0;i<4;i++) lt[i] = ftanh(nc[i]*sc);
    }
    float nlt = sqrtf(wdot<4>(lt,lt)+1e-15f);
    float nh[4];
    pwmulp_k(op, lt, nlt, nh);
    st4(out + 0*NN*128 + b, nh);
    st4(out + 1*NN*128 + b, nc);
  }

  // ---- Sphere
  {
    float cc[4] = {0,0,0,0};
    float y2c;
    {
      float d2 = 0.f;
      #pragma unroll
      for(int k=0;k<8;k++){
        float pv[4]; ld4(pv, g_P2 + j8[k]*128 + l*4);
        float lam = g_lam2[j8[k]];
        #pragma unroll
        for(int i=0;i<4;i++) cc[i] += lam*pv[i];
        d2 += lam - 1.f;
      }
      float den = fmaxf(fabsf(d2), EPSF);
      float nnum = sqrtf(wdot<4>(cc,cc) + 1e-15f);
      float nn = __fdividef(nnum, den);
      float m = ftan(0.5f*atanf(nn));
      float st = __fdividef(m, nnum);
      #pragma unroll
      for(int i=0;i<4;i++) cc[i] *= st;
      y2c = m*m;
    }
    float z[12], io[12];
    #pragma unroll
    for(int c=0;c<3;c++){ ld4(z+4*c, g_Z2 + b3 + 128*c); ld4(io+4*c, iou2 + b3 + 128*c); }
    float nz = sqrtf(wdot<12>(z,z)+1e-15f);
    float mz = ftan(nz);
    {
      float sc = __fdividef(mz, nz);
      #pragma unroll
      for(int i=0;i<12;i++) z[i] *= sc;
    }
    float x2 = wdot<12>(io,io);
    float xy = wdot<12>(io,z);
    float y2 = mz*mz;
    float cx = 1.f-2.f*xy-y2, cy = 1.f+x2;
    float idn = __fdividef(1.f, safe_den(1.f-2.f*xy+x2*y2));
    float ni[12];
    #pragma unroll
    for(int i=0;i<12;i++) ni[i] = (cx*io[i] + cy*z[i])*idn;
    float ip[4], op[4], up[4];
    {
      float n0 = sqrtf(wdot<4>(ni,ni)+1e-15f);
      float s0 = __fdividef(atanf(n0), n0);
      float n1 = sqrtf(wdot<4>(ni+4,ni+4)+1e-15f);
      float s1 = __fdividef(atanf(n1), n1);
      float n2 = sqrtf(wdot<4>(ni+8,ni+8)+1e-15f);
      float s2 = __fdividef(atanf(n2), n2);
      #pragma unroll
      for(int i=0;i<4;i++){
        ip[i] = fsig(ni[i]*s0);
        op[i] = fsig(ni[4+i]*s1);
        up[i] = ftanh(ni[8+i]*s2);
      }
    }
    float nup = sqrtf(wdot<4>(up,up)+1e-15f);
    float t[4];
    float mt = pwmuls_k(ip, up, nup, t);
    float xys = 0.f;
    #pragma unroll
    for(int i=0;i<4;i++) xys += t[i]*cc[i];
    float xyc = wred(xys);
    float x2c = mt*mt;
    float cxc = 1.f-2.f*xyc-y2c, cyc = 1.f+x2c;
    float idnc = __fdividef(1.f, safe_den(1.f-2.f*xyc+x2c*y2c));
    float nc[4];
    #pragma unroll
    for(int i=0;i<4;i++) nc[i] = (cxc*t[i] + cyc*cc[i])*idnc;
    float n2nc = fmaxf((cxc*cxc*x2c + 2.f*cxc*cyc*xyc + cyc*cyc*y2c)*idnc*idnc, 0.f);
    float nnc = sqrtf(n2nc + 1e-15f);
    float lt[4];
    {
      float sc = __fdividef(atanf(nnc), nnc);
      #pragma unroll
      for(int i=0;i<4;i++) lt[i] = ftanh(nc[i]*sc);
    }
    float nlt = sqrtf(wdot<4>(lt,lt)+1e-15f);
    float nh[4];
    pwmuls_k(op, lt, nlt, nh);
    st4(out + 2*NN*128 + b, nh);
    st4(out + 3*NN*128 + b, nc);
  }

  // ---- Euclid
  {
    float cc[4] = {0,0,0,0};
    #pragma unroll
    for(int k=0;k<8;k++){
      float ev[4]; ld4(ev, g_E3 + j8[k]*128 + l*4);
      #pragma unroll
      for(int i=0;i<4;i++) cc[i] += ev[i];
    }
    float z[12], io[12];
    #pragma unroll
    for(int c=0;c<3;c++){ ld4(z+4*c, g_Z3 + b3 + 128*c); ld4(io+4*c, iou3 + b3 + 128*c); }
    float nc[4], nh[4];
    #pragma unroll
    for(int i=0;i<4;i++){
      float ip = fsig(io[i]   + z[i]);
      float op = fsig(io[4+i] + z[4+i]);
      float up = ftanh(io[8+i] + z[8+i]);
      nc[i] = ip*up + cc[i];
      nh[i] = op*ftanh(nc[i]);
    }
    st4(out + 4*NN*128 + b, nh);
    st4(out + 5*NN*128 + b, nc);
  }
}

// ----------------------------- launch -----------------------------
extern "C" void kernel_launch(void* const* d_in, const int* in_sizes, int n_in,
                              void* d_out, int out_size){
  const float* x     = (const float*)d_in[0];
  const float* h1    = (const float*)d_in[1];
  const float* c1    = (const float*)d_in[2];
  const float* h2    = (const float*)d_in[3];
  const float* c2    = (const float*)d_in[4];
  const float* h3    = (const float*)d_in[5];
  const float* c3    = (const float*)d_in[6];
  const float* del_t = (const float*)d_in[7];
  const float* iou1  = (const float*)d_in[8];
  const float* iou2  = (const float*)d_in[9];
  const float* iou3  = (const float*)d_in[10];
  const float* Wq_w  = (const float*)d_in[11];
  const float* Wq_b  = (const float*)d_in[12];
  const float* Wc_w  = (const float*)d_in[13];
  const float* Wc_b  = (const float*)d_in[14];
  const float* Uf_w  = (const float*)d_in[15];
  const float* Uf_b  = (const float*)d_in[16];
  const float* Up_w  = (const float*)d_in[17];
  const float* Up_b  = (const float*)d_in[18];
  const float* Uiou_w= (const float*)d_in[19];
  const float* Uiou_b= (const float*)d_in[20];
  const float* dptr  = (const float*)d_in[21];
  const int*   nbr   = (const int*)d_in[22];
  float* out = (float*)d_out;

  cudaFuncSetAttribute(k_gemm1, cudaFuncAttributeMaxDynamicSharedMemorySize, GSMEM);
  cudaFuncSetAttribute(k_gemm2, cudaFuncAttributeMaxDynamicSharedMemorySize, GSMEM);

  k_prep<<<NN/8 + 224, 256>>>(h1, h2, c1, c2, x, h3, c3, Wq_w, Wc_w, Uf_w, Up_w, Uiou_w);
  k_gemm1<<<dim3(NN/64, 1, 10), 256, GSMEM>>>(Wq_b, Wc_b, Uf_b, Up_b);
  k_node<<<dim3(NN/8, 2), 256>>>(h1, h2, h3, c1, c2, c3, del_t, dptr);
  k_attn<<<NN/8, 256>>>(nbr);
  k_gemm2<<<dim3(NN/64, 3, 3), 256, GSMEM>>>(Uiou_b);
  k_final<<<NN/8, 256>>>(iou1, iou2, iou3, nbr, out);
}

// round 15
// speedup vs baseline: 1.0388x; 1.0388x over previous
#include <cuda_runtime.h>
#include <cuda_bf16.h>
#include <math.h>
#include <stdint.h>

#define NN 8192
#define HH 128
#define H3 384
#define EPSF 1e-6f
#define PMF 0.9999f
#define PADH 36
#define GSMEM (384 * PADH * 4)

// ----------------------------- fp32 scratch -----------------------------
__device__ float g_Yq[NN*HH];
__device__ float g_Yup1[NN*HH], g_Yup2[NN*HH], g_Yup3[NN*HH];
__device__ float g_Yuf1[NN*HH], g_Yuf2[NN*HH], g_Yuf3[NN*HH];
__device__ float g_Ywc1[NN*HH], g_Ywc2[NN*HH], g_Ywc3[NN*HH];
__device__ float g_h1p[NN*HH], g_h1s[NN*HH], g_h1e[NN*HH];
__device__ float g_P1[NN*HH], g_P2[NN*HH], g_E3[NN*HH];
__device__ float g_c1o[NN*HH], g_c2o[NN*HH], g_c3o[NN*HH];
__device__ float g_Z1[NN*H3], g_Z2[NN*H3], g_Z3[NN*H3];
// per-node scalars
__device__ float g_y2p[NN], g_y2s[NN], g_lam1[NN], g_lam2[NN];
__device__ float g_nh1[NN], g_nh2[NN];
__device__ float g_n2c1o[NN], g_n2c2o[NN];
// bf16 hi/lo packed
__device__ uint32_t g_xh[NN*64],  g_xl[NN*64];
__device__ uint32_t g_l1h[NN*64], g_l1l[NN*64];
__device__ uint32_t g_l2h[NN*64], g_l2l[NN*64];
__device__ uint32_t g_h3h[NN*64], g_h3l[NN*64];
__device__ uint32_t g_lc1h[NN*64], g_lc1l[NN*64];
__device__ uint32_t g_lc2h[NN*64], g_lc2l[NN*64];
__device__ uint32_t g_c3h[NN*64], g_c3l[NN*64];
__device__ uint32_t g_A1h[NN*64], g_A1l[NN*64];
__device__ uint32_t g_A2h[NN*64], g_A2l[NN*64];
__device__ uint32_t g_A3h[NN*64], g_A3l[NN*64];
__device__ uint32_t g_Wqh[128*64], g_Wql[128*64];
__device__ uint32_t g_Wch[128*64], g_Wcl[128*64];
__device__ uint32_t g_Ufh[128*64], g_Ufl[128*64];
__device__ uint32_t g_Uph[128*64], g_Upl[128*64];
__device__ uint32_t g_Uih[384*64], g_Uil[384*64];

// ----------------------------- fast math -----------------------------
__device__ __forceinline__ float ftanh(float x){
  float a = fabsf(x);
  float r;
  if(a < 0.105f){
    float a2 = a*a;
    r = a*(1.f - a2*(0.33333334f - a2*0.13333334f));
  } else {
    float t = __expf(-2.f*a);
    r = __fdividef(1.f - t, 1.f + t);
  }
  return copysignf(r, x);
}
__device__ __forceinline__ float fatanh(float u){
  u = fminf(fmaxf(u, -1.f + 1e-5f), 1.f - 1e-5f);
  float a = fabsf(u);
  float r;
  if(a < 0.105f){
    float a2 = a*a;
    r = a*(1.f + a2*(0.33333334f + a2*0.2f));
  } else {
    r = 0.5f*__logf(__fdividef(1.f + a, 1.f - a));
  }
  return copysignf(r, u);
}
__device__ __forceinline__ float fsig(float x){
  return __fdividef(1.f, 1.f + __expf(-x));
}
__device__ __forceinline__ float ftan(float u){
  u = fminf(fmaxf(u, -1.47079f), 1.47079f);
  return __tanf(u);
}
__device__ __forceinline__ float safe_den(float d){
  return d >= 0.f ? fmaxf(d, EPSF) : fminf(d, -EPSF);
}

// ----------------------------- warp helpers -----------------------------
__device__ __forceinline__ float wred(float s){
  #pragma unroll
  for(int o=16;o;o>>=1) s += __shfl_xor_sync(0xffffffffu, s, o);
  return s;
}
template<int R> __device__ __forceinline__ float wdot(const float* a, const float* b){
  float s=0.f;
  #pragma unroll
  for(int i=0;i<R;i++) s += a[i]*b[i];
  return wred(s);
}
__device__ __forceinline__ void ld4(float* v, const float* p){
  float4 t = *(const float4*)p; v[0]=t.x; v[1]=t.y; v[2]=t.z; v[3]=t.w;
}
__device__ __forceinline__ void st4(float* p, const float* v){
  *(float4*)p = make_float4(v[0],v[1],v[2],v[3]);
}

__device__ __forceinline__ float pwmulp_k(const float* w, const float* x, float nx, float* o){
  float wx[4];
  #pragma unroll
  for(int i=0;i<4;i++) wx[i] = w[i]*x[i];
  float nwx = sqrtf(wdot<4>(wx,wx) + 1e-15f);
  float m = fminf(ftanh(__fdividef(nwx,nx)*fatanh(nx)), PMF);
  float s = __fdividef(m, nwx);
  #pragma unroll
  for(int i=0;i<4;i++) o[i] = wx[i]*s;
  return m;
}
__device__ __forceinline__ float pwmuls_k(const float* w, const float* x, float nx, float* o){
  float wx[4];
  #pragma unroll
  for(int i=0;i<4;i++) wx[i] = w[i]*x[i];
  float nwx = sqrtf(wdot<4>(wx,wx) + 1e-15f);
  float m = ftan(__fdividef(nwx,nx)*atanf(nx));
  float s = __fdividef(m, nwx);
  #pragma unroll
  for(int i=0;i<4;i++) o[i] = wx[i]*s;
  return m;
}
__device__ __forceinline__ void softmax8(float* s){
  float m = s[0];
  #pragma unroll
  for(int k=1;k<8;k++) m = fmaxf(m, s[k]);
  float sum = 0.f;
  #pragma unroll
  for(int k=0;k<8;k++){ s[k] = __expf(s[k]-m); sum += s[k]; }
  float inv = __fdividef(1.f, sum);
  #pragma unroll
  for(int k=0;k<8;k++) s[k] *= inv;
}

// ----------------------------- bf16 packing -----------------------------
__device__ __forceinline__ uint32_t pack_bf2(float f0, float f1){
  __nv_bfloat16 b0 = __float2bfloat16_rn(f0);
  __nv_bfloat16 b1 = __float2bfloat16_rn(f1);
  return ((uint32_t)__bfloat16_as_ushort(b1)<<16) | (uint32_t)__bfloat16_as_ushort(b0);
}
__device__ __forceinline__ void split_bf2(float f0, float f1, uint32_t& hi, uint32_t& lo){
  __nv_bfloat16 b0 = __float2bfloat16_rn(f0);
  __nv_bfloat16 b1 = __float2bfloat16_rn(f1);
  hi = ((uint32_t)__bfloat16_as_ushort(b1)<<16) | (uint32_t)__bfloat16_as_ushort(b0);
  lo = pack_bf2(f0 - __bfloat162float(b0), f1 - __bfloat162float(b1));
}
__device__ __forceinline__ void pack_store(uint32_t* dh, uint32_t* dl, int idx, const float* v){
  uint32_t h0,l0,h1,l1;
  split_bf2(v[0],v[1],h0,l0);
  split_bf2(v[2],v[3],h1,l1);
  *(uint2*)(dh+idx) = make_uint2(h0,h1);
  *(uint2*)(dl+idx) = make_uint2(l0,l1);
}

// ----------------------------- GEMM (bf16 3-term, ldmatrix, K-split for 4 blk/SM) -----------------------------
__device__ __forceinline__ void mma16(float* d, const uint32_t* a, const uint32_t* b){
  asm volatile("mma.sync.aligned.m16n8k16.row.col.f32.bf16.bf16.f32 "
    "{%0,%1,%2,%3},{%4,%5,%6,%7},{%8,%9},{%0,%1,%2,%3};"
    : "+f"(d[0]),"+f"(d[1]),"+f"(d[2]),"+f"(d[3])
    : "r"(a[0]),"r"(a[1]),"r"(a[2]),"r"(a[3]),"r"(b[0]),"r"(b[1]));
}
__device__ __forceinline__ void ldsm4(uint32_t& r0, uint32_t& r1, uint32_t& r2, uint32_t& r3, uint32_t addr){
  asm volatile("ldmatrix.sync.aligned.m8n8.x4.shared.b16 {%0,%1,%2,%3}, [%4];"
    : "=r"(r0),"=r"(r1),"=r"(r2),"=r"(r3) : "r"(addr));
}

__device__ __forceinline__ void gemm_pk(const uint32_t* __restrict__ AhG, const uint32_t* __restrict__ AlG,
                                        const uint32_t* __restrict__ BhG, const uint32_t* __restrict__ BlG,
                                        const float* __restrict__ bias, float* __restrict__ C, int HO){
  extern __shared__ uint32_t sh[];
  uint32_t* Ah = sh;
  uint32_t* Al = sh + 64*PADH;
  uint32_t* Bh = sh + 128*PADH;
  uint32_t* Bl = sh + 256*PADH;
  const int m0 = blockIdx.x*64;
  const int n0 = blockIdx.y*128;
  const int t = threadIdx.x;
  const int lane = t & 31, w = t >> 5;
  const int wm = w >> 2, wn = w & 3;
  const int gid = lane >> 2, tig = lane & 3;

  uint32_t shbase = (uint32_t)__cvta_generic_to_shared(sh);
  int rowA = wm*32 + (lane & 15);
  int colA = ((lane >> 4) & 1) * 4;
  uint32_t aAh0 = shbase + (uint32_t)((rowA*PADH + colA) * 4);
  uint32_t aAh1 = aAh0 + 16u*PADH*4u;
  uint32_t aAl0 = aAh0 + 64u*PADH*4u;
  uint32_t aAl1 = aAh1 + 64u*PADH*4u;
  int rowB = wn*32 + ((lane >> 4) & 1) * 8 + (lane & 7);
  int colB = ((lane >> 3) & 1) * 4;
  uint32_t aBh0 = shbase + (uint32_t)((128*PADH + rowB*PADH + colB) * 4);
  uint32_t aBh1 = aBh0 + 16u*PADH*4u;
  uint32_t aBl0 = aBh0 + 128u*PADH*4u;
  uint32_t aBl1 = aBh1 + 128u*PADH*4u;

  float acc[2][4][4];
  #pragma unroll
  for(int mt=0;mt<2;mt++)
    #pragma unroll
    for(int nt=0;nt<4;nt++)
      #pragma unroll
      for(int i=0;i<4;i++) acc[mt][nt][i]=0.f;

  #pragma unroll
  for(int half=0; half<2; half++){
    int c0 = half*32;
    if(half) __syncthreads();
    #pragma unroll
    for(int i=0;i<2;i++){
      int p = t + i*256; int r = p>>3, c = (p&7)*4;
      *(uint4*)(Ah + r*PADH + c) = *(const uint4*)(AhG + (m0+r)*64 + c0 + c);
      *(uint4*)(Al + r*PADH + c) = *(const uint4*)(AlG + (m0+r)*64 + c0 + c);
    }
    #pragma unroll
    for(int i=0;i<4;i++){
      int p = t + i*256; int r = p>>3, c = (p&7)*4;
      *(uint4*)(Bh + r*PADH + c) = *(const uint4*)(BhG + (n0+r)*64 + c0 + c);
      *(uint4*)(Bl + r*PADH + c) = *(const uint4*)(BlG + (n0+r)*64 + c0 + c);
    }
    __syncthreads();
    #pragma unroll
    for(int s=0;s<4;s++){
      uint32_t ko = (uint32_t)(s*8*4);
      uint32_t ah[2][4], al[2][4], bh[4][2], bl[4][2];
      ldsm4(ah[0][0], ah[0][1], ah[0][2], ah[0][3], aAh0 + ko);
      ldsm4(ah[1][0], ah[1][1], ah[1][2], ah[1][3], aAh1 + ko);
      ldsm4(al[0][0], al[0][1], al[0][2], al[0][3], aAl0 + ko);
      ldsm4(al[1][0], al[1][1], al[1][2], al[1][3], aAl1 + ko);
      ldsm4(bh[0][0], bh[0][1], bh[1][0], bh[1][1], aBh0 + ko);
      ldsm4(bh[2][0], bh[2][1], bh[3][0], bh[3][1], aBh1 + ko);
      ldsm4(bl[0][0], bl[0][1], bl[1][0], bl[1][1], aBl0 + ko);
      ldsm4(bl[2][0], bl[2][1], bl[3][0], bl[3][1], aBl1 + ko);
      #pragma unroll
      for(int mt=0;mt<2;mt++)
        #pragma unroll
        for(int nt=0;nt<4;nt++){
          mma16(acc[mt][nt], al[mt], bh[nt]);
          mma16(acc[mt][nt], ah[mt], bl[nt]);
          mma16(acc[mt][nt], ah[mt], bh[nt]);
        }
    }
  }

  #pragma unroll
  for(int mt=0;mt<2;mt++){
    int r = m0 + wm*32 + mt*16 + gid;
    #pragma unroll
    for(int nt=0;nt<4;nt++){
      int c = n0 + wn*32 + nt*8 + tig*2;
      float b0 = bias[c], b1 = bias[c+1];
      *(float2*)(C + r*HO + c)     = make_float2(acc[mt][nt][0]+b0, acc[mt][nt][1]+b1);
      *(float2*)(C + (r+8)*HO + c) = make_float2(acc[mt][nt][2]+b0, acc[mt][nt][3]+b1);
    }
  }
}

__global__ void __launch_bounds__(256) k_gemm1(const float* __restrict__ bq, const float* __restrict__ bc,
                                               const float* __restrict__ bf, const float* __restrict__ bp){
  const uint32_t *Ah,*Al,*Bh,*Bl; const float* B; float* C;
  switch(blockIdx.z){
    case 0: Ah=g_xh;  Al=g_xl;  Bh=g_Wqh; Bl=g_Wql; B=bq; C=g_Yq;   break;
    case 1: Ah=g_l1h; Al=g_l1l; Bh=g_Uph; Bl=g_Upl; B=bp; C=g_Yup1; break;
    case 2: Ah=g_l2h; Al=g_l2l; Bh=g_Uph; Bl=g_Upl; B=bp; C=g_Yup2; break;
    case 3: Ah=g_h3h; Al=g_h3l; Bh=g_Uph; Bl=g_Upl; B=bp; C=g_Yup3; break;
    case 4: Ah=g_l1h; Al=g_l1l; Bh=g_Ufh; Bl=g_Ufl; B=bf; C=g_Yuf1; break;
    case 5: Ah=g_l2h; Al=g_l2l; Bh=g_Ufh; Bl=g_Ufl; B=bf; C=g_Yuf2; break;
    case 6: Ah=g_h3h; Al=g_h3l; Bh=g_Ufh; Bl=g_Ufl; B=bf; C=g_Yuf3; break;
    case 7: Ah=g_lc1h;Al=g_lc1l;Bh=g_Wch; Bl=g_Wcl; B=bc; C=g_Ywc1; break;
    case 8: Ah=g_lc2h;Al=g_lc2l;Bh=g_Wch; Bl=g_Wcl; B=bc; C=g_Ywc2; break;
    default:Ah=g_c3h; Al=g_c3l; Bh=g_Wch; Bl=g_Wcl; B=bc; C=g_Ywc3; break;
  }
  gemm_pk(Ah, Al, Bh, Bl, B, C, 128);
}

__global__ void __launch_bounds__(256) k_gemm2(const float* __restrict__ bi){
  const uint32_t *Ah,*Al; float* C;
  switch(blockIdx.z){
    case 0: Ah=g_A1h; Al=g_A1l; C=g_Z1; break;
    case 1: Ah=g_A2h; Al=g_A2l; C=g_Z2; break;
    default:Ah=g_A3h; Al=g_A3l; C=g_Z3; break;
  }
  gemm_pk(Ah, Al, g_Uih, g_Uil, bi, C, 384);
}

// ----------------------------- prep -----------------------------
__global__ void k_prep(const float* __restrict__ h1, const float* __restrict__ h2,
                       const float* __restrict__ c1, const float* __restrict__ c2,
                       const float* __restrict__ x,  const float* __restrict__ h3,
                       const float* __restrict__ c3,
                       const float* __restrict__ Wq, const float* __restrict__ Wc,
                       const float* __restrict__ Uf, const float* __restrict__ Up,
                       const float* __restrict__ Ui){
  if(blockIdx.x >= NN/8){
    int i = (blockIdx.x - NN/8)*256 + threadIdx.x;
    const float* src; uint32_t *dh, *dl; int off;
    if(i < 8192){ src=Wq; dh=g_Wqh; dl=g_Wql; off=i; }
    else if(i < 16384){ src=Wc; dh=g_Wch; dl=g_Wcl; off=i-8192; }
    else if(i < 24576){ src=Uf; dh=g_Ufh; dl=g_Ufl; off=i-16384; }
    else if(i < 32768){ src=Up; dh=g_Uph; dl=g_Upl; off=i-24576; }
    else if(i < 57344){ src=Ui; dh=g_Uih; dl=g_Uil; off=i-32768; }
    else return;
    float2 v = *(const float2*)(src + off*2);
    uint32_t hi, lo; split_bf2(v.x, v.y, hi, lo);
    dh[off]=hi; dl[off]=lo;
    return;
  }
  int nd = (blockIdx.x*blockDim.x + threadIdx.x) >> 5;
  int l = threadIdx.x & 31;
  int b = nd*128 + l*4;
  int bi = nd*64 + l*2;
  float v[4], w[4];
  ld4(v, h1+b);
  float nr = sqrtf(wdot<4>(v,v) + 1e-15f);
  float s = __fdividef(fatanh(nr), nr);
  #pragma unroll
  for(int i=0;i<4;i++) w[i]=v[i]*s;
  pack_store(g_l1h,g_l1l,bi,w);
  if(l==0) g_nh1[nd] = nr;
  ld4(v, h2+b);
  nr = sqrtf(wdot<4>(v,v) + 1e-15f);
  s = __fdividef(atanf(nr), nr);
  #pragma unroll
  for(int i=0;i<4;i++) w[i]=v[i]*s;
  pack_store(g_l2h,g_l2l,bi,w);
  if(l==0) g_nh2[nd] = nr;
  ld4(v, c1+b);
  nr = sqrtf(wdot<4>(v,v) + 1e-15f);
  s = __fdividef(fatanh(nr), nr);
  #pragma unroll
  for(int i=0;i<4;i++) w[i]=v[i]*s;
  pack_store(g_lc1h,g_lc1l,bi,w);
  ld4(v, c2+b);
  nr = sqrtf(wdot<4>(v,v) + 1e-15f);
  s = __fdividef(atanf(nr), nr);
  #pragma unroll
  for(int i=0;i<4;i++) w[i]=v[i]*s;
  pack_store(g_lc2h,g_lc2l,bi,w);
  ld4(v, x+b);  pack_store(g_xh, g_xl, bi, v);
  ld4(v, h3+b); pack_store(g_h3h,g_h3l,bi, v);
  ld4(v, c3+b); pack_store(g_c3h,g_c3l,bi, v);
}

// ----------------------------- per-node elementwise (split 2-way, reg-capped) -----------------------------
__global__ void __launch_bounds__(256, 4) k_node(const float* __restrict__ h1, const float* __restrict__ h2,
                       const float* __restrict__ h3, const float* __restrict__ c1,
                       const float* __restrict__ c2, const float* __restrict__ c3,
                       const float* __restrict__ del_t, const float* __restrict__ dptr){
  int nd = (blockIdx.x*blockDim.x + threadIdx.x) >> 5;
  if(nd >= NN) return;
  int l = threadIdx.x & 31;
  int b = nd*128 + l*4;

  if(blockIdx.y == 0){
    float s1[4];
    {
      ld4(s1, g_Yup1+b);
      float nt = sqrtf(wdot<4>(s1,s1)+1e-15f);
      float me = fminf(ftanh(nt), PMF);
      float sc = __fdividef(me, nt);
      #pragma unroll
      for(int i=0;i<4;i++) s1[i] = fsig(s1[i]*sc);
      float ns = sqrtf(wdot<4>(s1,s1)+1e-15f);
      float sl = __fdividef(fatanh(ns), ns);
      #pragma unroll
      for(int i=0;i<4;i++) s1[i] *= sl;
    }
    float s2[4];
    {
      ld4(s2, g_Yup2+b);
      float nt = sqrtf(wdot<4>(s2,s2)+1e-15f);
      float me = ftan(nt);
      float sc = __fdividef(me, nt);
      #pragma unroll
      for(int i=0;i<4;i++) s2[i] = fsig(s2[i]*sc);
      float ns = sqrtf(wdot<4>(s2,s2)+1e-15f);
      float sl = __fdividef(atanf(ns), ns);
      #pragma unroll
      for(int i=0;i<4;i++) s2[i] *= sl;
    }
    float s3[4]; ld4(s3, g_Yup3+b);
    #pragma unroll
    for(int i=0;i<4;i++) s3[i] = fsig(s3[i]);

    float h1v[4],h2v[4],h3v[4];
    ld4(h1v, h1+b); ld4(h2v, h2+b); ld4(h3v, h3+b);
    float nh1 = g_nh1[nd], nh2 = g_nh2[nd];
    float nh3 = sqrtf(wdot<4>(h3v,h3v)+1e-15f);

    float ht1p[4], ht2p[4], ht3p[4], tmp[4];
    float m1p = pwmulp_k(s1, h1v, nh1, ht1p);
    float m2p, m3p;
    {
      float mm = fminf(ftanh(atanf(nh2)), PMF);
      float sc = __fdividef(mm, nh2);
      #pragma unroll
      for(int i=0;i<4;i++) tmp[i] = h2v[i]*sc;
      m2p = pwmulp_k(s2, tmp, mm, ht2p);
    }
    {
      float mm = fminf(ftanh(nh3), PMF);
      float sc = __fdividef(mm, nh3);
      #pragma unroll
      for(int i=0;i<4;i++) tmp[i] = h3v[i]*sc;
      m3p = pwmulp_k(s3, tmp, mm, ht3p);
    }
    {
      float la = __fdividef(2.f, 1.f-m1p*m1p);
      float lb = __fdividef(2.f, 1.f-m2p*m2p);
      float lc = __fdividef(2.f, 1.f-m3p*m3p);
      float den = fmaxf(fabsf(la+lb+lc-3.f), EPSF);
      float num[4];
      #pragma unroll
      for(int i=0;i<4;i++) num[i] = la*ht1p[i]+lb*ht2p[i]+lc*ht3p[i];
      float nnum = sqrtf(wdot<4>(num,num)+1e-15f);
      float nn = __fdividef(nnum, den);
      float m = fminf(ftanh(0.5f*fatanh(nn)), PMF);
      float sc = __fdividef(3.f*m, nnum);
      #pragma unroll
      for(int i=0;i<4;i++) num[i] *= sc;
      st4(g_h1p+b, num);
      if(l==0) g_y2p[nd] = 9.f*m*m;
    }

    float ht1s[4], ht2s[4], ht3s[4];
    float m2s;
    {
      float nl1 = fatanh(nh1);
      float mm = ftan(nl1);
      float sc = __fdividef(mm, nh1);
      #pragma unroll
      for(int i=0;i<4;i++) tmp[i] = h1v[i]*sc;
      float m1s = pwmulp_k(s1, tmp, mm, ht1s);
      m2s = pwmuls_k(s2, h2v, nh2, ht2s);
      float mm3 = ftan(nh3);
      float sc3 = __fdividef(mm3, nh3);
      #pragma unroll
      for(int i=0;i<4;i++) tmp[i] = h3v[i]*sc3;
      float m3s = pwmuls_k(s3, tmp, mm3, ht3s);
      float la = __fdividef(2.f, 1.f-m1s*m1s);
      float lb = __fdividef(2.f, 1.f-m2s*m2s);
      float lc = __fdividef(2.f, 1.f-m3s*m3s);
      float den = fmaxf(fabsf(la+lb+lc-3.f), EPSF);
      float num[4];
      #pragma unroll
      for(int i=0;i<4;i++) num[i] = la*ht1s[i]+lb*ht2s[i]+lc*ht3s[i];
      float nnum = sqrtf(wdot<4>(num,num)+1e-15f);
      float nn = __fdividef(nnum, den);
      float m = fminf(ftanh(0.5f*fatanh(nn)), PMF);
      float sc2 = __fdividef(3.f*m, nnum);
      #pragma unroll
      for(int i=0;i<4;i++) num[i] *= sc2;
      st4(g_h1s+b, num);
      if(l==0) g_y2s[nd] = 9.f*m*m;
    }

    {
      float e1s = __fdividef(fatanh(m1p), m1p);
      float e2s = __fdividef(atanf(m2s), m2s);
      float he[4];
      #pragma unroll
      for(int i=0;i<4;i++) he[i] = ht1p[i]*e1s + ht2s[i]*e2s + s3[i]*h3v[i];
      st4(g_h1e+b, he);
    }
  } else {
    float g = __fdividef(dptr[0], del_t[nd] + 1.f);
    float nx2 = sqrtf(g*g + 1e-15f);
    float ax2 = fatanh(nx2);
    float sx2 = atanf(nx2);

    // Poincare cell
    {
      float c1v[4]; ld4(c1v, c1+b);
      float cw[4]; ld4(cw, g_Ywc1+b);
      float nw = sqrtf(wdot<4>(cw,cw)+1e-15f);
      {
        float sc = __fdividef(fatanh(fminf(ftanh(nw),PMF)), nw);
        #pragma unroll
        for(int i=0;i<4;i++) cw[i] = ftanh(cw[i]*sc);
      }
      float nck = sqrtf(wdot<4>(cw,cw)+1e-15f);
      float mk = fminf(ftanh(nck), PMF);
      {
        float sc = __fdividef(mk, nck);
        #pragma unroll
        for(int i=0;i<4;i++) cw[i] *= sc;
      }
      float x2 = mk*mk;
      float y2 = wdot<4>(c1v,c1v);
      float xys = 0.f;
      #pragma unroll
      for(int i=0;i<4;i++) xys -= cw[i]*c1v[i];
      float xy = wred(xys);
      float cx = 1.f+2.f*xy+y2, cy = 1.f-x2;
      float idn = __fdividef(1.f, safe_den(1.f+2.f*xy+x2*y2));
      float t1[4];
      #pragma unroll
      for(int i=0;i<4;i++) t1[i] = (cx*(-cw[i]) + cy*c1v[i])*idn;
      float n2t1 = fmaxf((cx*cx*x2 + 2.f*cx*cy*xy + cy*cy*y2)*idn*idn, 0.f);
      if(n2t1 > PMF*PMF){
        float sc = PMF*rsqrtf(n2t1);
        #pragma unroll
        for(int i=0;i<4;i++) t1[i] *= sc;
        n2t1 = PMF*PMF;
      }
      float m2 = fminf(ftanh(__fdividef(g*mk, nx2)*ax2), PMF);
      float t2s = __fdividef(m2, mk);
      float xys2 = 0.f;
      #pragma unroll
      for(int i=0;i<4;i++) xys2 += t1[i]*cw[i]*t2s;
      float xy2 = wred(xys2);
      x2 = n2t1; y2 = m2*m2;
      cx = 1.f+2.f*xy2+y2; cy = 1.f-x2;
      idn = __fdividef(1.f, safe_den(1.f+2.f*xy2+x2*y2));
      float ck[4];
      #pragma unroll
      for(int i=0;i<4;i++) ck[i] = (cx*t1[i] + cy*cw[i]*t2s)*idn;
      float n2ck = fmaxf((cx*cx*x2 + 2.f*cx*cy*xy2 + cy*cy*y2)*idn*idn, 0.f);
      float nckt = sqrtf(n2ck + 1e-15f);
      if(nckt > PMF){
        float sc = __fdividef(PMF, nckt);
        #pragma unroll
        for(int i=0;i<4;i++) ck[i] *= sc;
        nckt = PMF;
      }
      float fp[4]; ld4(fp, g_Yuf1+b);
      float nf = sqrtf(wdot<4>(fp,fp)+1e-15f);
      float scf = __fdividef(fatanh(fminf(ftanh(nf),PMF)), nf);
      #pragma unroll
      for(int i=0;i<4;i++) fp[i] = fsig(fp[i]*scf);
      float P1[4];
      float mP1 = pwmulp_k(fp, ck, nckt, P1);
      st4(g_P1+b, P1);
      if(l==0) g_lam1[nd] = __fdividef(2.f, 1.f-mP1*mP1);
    }

    // Sphere cell
    {
      float c2v[4]; ld4(c2v, c2+b);
      float cw[4]; ld4(cw, g_Ywc2+b);
      float nw = sqrtf(wdot<4>(cw,cw)+1e-15f);
      {
        float sc = __fdividef(atanf(ftan(nw)), nw);
        #pragma unroll
        for(int i=0;i<4;i++) cw[i] = ftanh(cw[i]*sc);
      }
      float nck = sqrtf(wdot<4>(cw,cw)+1e-15f);
      float mk = ftan(nck);
      {
        float sc = __fdividef(mk, nck);
        #pragma unroll
        for(int i=0;i<4;i++) cw[i] *= sc;
      }
      float x2 = mk*mk;
      float y2 = wdot<4>(c2v,c2v);
      float xys = 0.f;
      #pragma unroll
      for(int i=0;i<4;i++) xys -= cw[i]*c2v[i];
      float xy = wred(xys);
      float cx = 1.f-2.f*xy-y2, cy = 1.f+x2;
      float idn = __fdividef(1.f, safe_den(1.f-2.f*xy+x2*y2));
      float t1[4];
      #pragma unroll
      for(int i=0;i<4;i++) t1[i] = (cx*(-cw[i]) + cy*c2v[i])*idn;
      float n2t1 = fmaxf((cx*cx*x2 + 2.f*cx*cy*xy + cy*cy*y2)*idn*idn, 0.f);
      float m2 = ftan(__fdividef(g*mk, nx2)*sx2);
      float t2s = __fdividef(m2, mk);
      float xys2 = 0.f;
      #pragma unroll
      for(int i=0;i<4;i++) xys2 += t1[i]*cw[i]*t2s;
      float xy2 = wred(xys2);
      x2 = n2t1; y2 = m2*m2;
      cx = 1.f-2.f*xy2-y2; cy = 1.f+x2;
      idn = __fdividef(1.f, safe_den(1.f-2.f*xy2+x2*y2));
      float ck[4];
      #pragma unroll
      for(int i=0;i<4;i++) ck[i] = (cx*t1[i] + cy*cw[i]*t2s)*idn;
      float n2ck = fmaxf((cx*cx*x2 + 2.f*cx*cy*xy2 + cy*cy*y2)*idn*idn, 0.f);
      float nckt = sqrtf(n2ck + 1e-15f);
      float fs[4]; ld4(fs, g_Yuf2+b);
      float nf = sqrtf(wdot<4>(fs,fs)+1e-15f);
      float scf = __fdividef(atanf(ftan(nf)), nf);
      #pragma unroll
      for(int i=0;i<4;i++) fs[i] = fsig(fs[i]*scf);
      float P2[4];
      float mP2 = pwmuls_k(fs, ck, nckt, P2);
      st4(g_P2+b, P2);
      if(l==0) g_lam2[nd] = __fdividef(2.f, 1.f+mP2*mP2);
    }

    // Euclid cell
    {
      float c3v[4]; ld4(c3v, c3+b);
      float cske[4]; ld4(cske, g_Ywc3+b);
      float fe[4]; ld4(fe, g_Yuf3+b);
      float E3[4];
      #pragma unroll
      for(int i=0;i<4;i++){
        float ck = ftanh(cske[i]);
        E3[i] = fsig(fe[i])*(c3v[i] - ck + ck*g);
      }
      st4(g_E3+b, E3);
    }
  }
}

// ----------------------------- gather + attention + cell reductions (R12 layout) -----------------------------
__global__ void __launch_bounds__(256, 4) k_attn(const int* __restrict__ nbr){
  int nd = (blockIdx.x*blockDim.x + threadIdx.x) >> 5;
  if(nd >= NN) return;
  int l = threadIdx.x & 31;
  int b = nd*128 + l*4;
  int bi = nd*64 + l*2;
  const int* nb = nbr + nd*8;
  int j8[8];
  #pragma unroll
  for(int k=0;k<8;k++) j8[k] = nb[k];

  float yq[4]; ld4(yq, g_Yq+b);
  float nq = sqrtf(wdot<4>(yq,yq) + 1e-15f);

  // ===== Section 1: Poincare attention =====
  {
    float mp = fminf(ftanh(nq), PMF);
    float x2 = mp*mp;
    float xq[4];
    float sp = __fdividef(mp, nq);
    #pragma unroll
    for(int i=0;i<4;i++) xq[i] = yq[i]*sp;
    float sc[8];
    #pragma unroll
    for(int k=0;k<8;k++){
      float hk[4]; ld4(hk, g_h1p + j8[k]*128 + l*4);
      float y2 = g_y2p[j8[k]];
      float s = 0.f;
      #pragma unroll
      for(int i=0;i<4;i++) s -= xq[i]*hk[i];
      float xy = wred(s);
      float cx = 1.f + 2.f*xy + y2;
      float cy = 1.f - x2;
      float dn = safe_den(1.f + 2.f*xy + x2*y2);
      float o2 = cx*cx*x2 + 2.f*cx*cy*xy + cy*cy*y2;
      float nr = fminf(__fdividef(sqrtf(fmaxf(o2,0.f) + 1e-15f), fabsf(dn)), PMF);
      sc[k] = -2.f*fatanh(nr);
    }
    softmax8(sc);
    float num[4] = {0,0,0,0};
    float ds = 0.f;
    #pragma unroll
    for(int k=0;k<8;k++){
      float hk[4]; ld4(hk, g_h1p + j8[k]*128 + l*4);
      float lam = __fdividef(2.f, 1.f - g_y2p[j8[k]]);
      float wk = sc[k]*lam;
      #pragma unroll
      for(int i=0;i<4;i++) num[i] += wk*hk[i];
      ds += sc[k]*(lam - 1.f);
    }
    float den = fmaxf(fabsf(ds), EPSF);
    float nnum = sqrtf(wdot<4>(num,num) + 1e-15f);
    float nn = __fdividef(nnum, den);
    float m = fminf(ftanh(0.5f*fatanh(nn)), PMF);
    float st = __fdividef(fatanh(m), nnum);
    #pragma unroll
    for(int i=0;i<4;i++) num[i] *= st;
    pack_store(g_A1h, g_A1l, bi, num);
  }

  // ===== Section 2: Sphere attention =====
  {
    float msp = ftan(nq);
    float x2 = msp*msp;
    float xq[4];
    float ss = __fdividef(msp, nq);
    #pragma unroll
    for(int i=0;i<4;i++) xq[i] = yq[i]*ss;
    float sc[8];
    #pragma unroll
    for(int k=0;k<8;k++){
      float hk[4]; ld4(hk, g_h1s + j8[k]*128 + l*4);
      float y2 = g_y2s[j8[k]];
      float s = 0.f;
      #pragma unroll
      for(int i=0;i<4;i++) s -= xq[i]*hk[i];
      float xy = wred(s);
      float cx = 1.f - 2.f*xy - y2;
      float cy = 1.f + x2;
      float dn = safe_den(1.f - 2.f*xy + x2*y2);
      float o2 = cx*cx*x2 + 2.f*cx*cy*xy + cy*cy*y2;
      float nr = __fdividef(sqrtf(fmaxf(o2,0.f) + 1e-15f), fabsf(dn));
      sc[k] = -2.f*atanf(nr);
    }
    softmax8(sc);
    float num[4] = {0,0,0,0};
    float ds = 0.f;
    #pragma unroll
    for(int k=0;k<8;k++){
      float hk[4]; ld4(hk, g_h1s + j8[k]*128 + l*4);
      float lam = __fdividef(2.f, 1.f + g_y2s[j8[k]]);
      float wk = sc[k]*lam;
      #pragma unroll
      for(int i=0;i<4;i++) num[i] += wk*hk[i];
      ds += sc[k]*(lam - 1.f);
    }
    float den = fmaxf(fabsf(ds), EPSF);
    float nnum = sqrtf(wdot<4>(num,num) + 1e-15f);
    float nn = __fdividef(nnum, den);
    float m = ftan(0.5f*atanf(nn));
    float st = __fdividef(atanf(m), nnum);
    #pragma unroll
    for(int i=0;i<4;i++) num[i] *= st;
    pack_store(g_A2h, g_A2l, bi, num);
  }

  // ===== Section 3: Euclid attention =====
  {
    const float isq = 0.08838834764831845f;
    float sc[8];
    #pragma unroll
    for(int k=0;k<8;k++){
      float hk[4]; ld4(hk, g_h1e + j8[k]*128 + l*4);
      float s = 0.f;
      #pragma unroll
      for(int i=0;i<4;i++) s += hk[i]*yq[i];
      sc[k] = wred(s)*isq;
    }
    softmax8(sc);
    float num[4] = {0,0,0,0};
    #pragma unroll
    for(int k=0;k<8;k++){
      float hk[4]; ld4(hk, g_h1e + j8[k]*128 + l*4);
      #pragma unroll
      for(int i=0;i<4;i++) num[i] += sc[k]*hk[i];
    }
    pack_store(g_A3h, g_A3l, bi, num);
  }

  // ===== Section 4: cell reductions (batched) =====
  {
    float c1[4]={0,0,0,0}, c2[4]={0,0,0,0}, c3[4]={0,0,0,0};
    float d1=0.f, d2=0.f;
    #pragma unroll
    for(int k=0;k<8;k++){
      int o = j8[k]*128 + l*4;
      float p1[4], p2[4], e3[4];
      ld4(p1, g_P1 + o); ld4(p2, g_P2 + o); ld4(e3, g_E3 + o);
      float lam1 = g_lam1[j8[k]], lam2 = g_lam2[j8[k]];
      #pragma unroll
      for(int i=0;i<4;i++){ c1[i] += lam1*p1[i]; c2[i] += lam2*p2[i]; c3[i] += e3[i]; }
      d1 += lam1 - 1.f;
      d2 += lam2 - 1.f;
    }
    {
      float den = fmaxf(fabsf(d1), EPSF);
      float nnum = sqrtf(wdot<4>(c1,c1) + 1e-15f);
      float nn = __fdividef(nnum, den);
      float m = fminf(ftanh(0.5f*fatanh(nn)), PMF);
      float st = __fdividef(m, nnum);
      #pragma unroll
      for(int i=0;i<4;i++) c1[i] *= st;
      st4(g_c1o+b, c1);
      if(l==0) g_n2c1o[nd] = m*m;
    }
    {
      float den = fmaxf(fabsf(d2), EPSF);
      float nnum = sqrtf(wdot<4>(c2,c2) + 1e-15f);
      float nn = __fdividef(nnum, den);
      float m = ftan(0.5f*atanf(nn));
      float st = __fdividef(m, nnum);
      #pragma unroll
      for(int i=0;i<4;i++) c2[i] *= st;
      st4(g_c2o+b, c2);
      if(l==0) g_n2c2o[nd] = m*m;
    }
    st4(g_c3o+b, c3);
  }
}

// ----------------------------- final epilogue (reg-capped) -----------------------------
__global__ void __launch_bounds__(256, 3) k_final(const float* __restrict__ iou1, const float* __restrict__ iou2,
                        const float* __restrict__ iou3, float* __restrict__ out){
  int nd = (blockIdx.x*blockDim.x + threadIdx.x) >> 5;
  if(nd >= NN) return;
  int l = threadIdx.x & 31;
  int b = nd*128 + l*4;
  int b3 = nd*384 + l*4;

  // ---- Poincare
  {
    float z[12], io[12];
    #pragma unroll
    for(int c=0;c<3;c++){ ld4(z+4*c, g_Z1 + b3 + 128*c); ld4(io+4*c, iou1 + b3 + 128*c); }
    float nz = sqrtf(wdot<12>(z,z)+1e-15f);
    float mz = fminf(ftanh(nz), PMF);
    {
      float sc = __fdividef(mz, nz);
      #pragma unroll
      for(int i=0;i<12;i++) z[i] *= sc;
    }
    float x2 = wdot<12>(io,io);
    float xy = wdot<12>(io,z);
    float y2 = mz*mz;
    float cx = 1.f+2.f*xy+y2, cy = 1.f-x2;
    float idn = __fdividef(1.f, safe_den(1.f+2.f*xy+x2*y2));
    float ni[12];
    #pragma unroll
    for(int i=0;i<12;i++) ni[i] = (cx*io[i] + cy*z[i])*idn;
    float n2ni = fmaxf((cx*cx*x2 + 2.f*cx*cy*xy + cy*cy*y2)*idn*idn, 0.f);
    if(n2ni > PMF*PMF){
      float sc = PMF*rsqrtf(n2ni);
      #pragma unroll
      for(int i=0;i<12;i++) ni[i] *= sc;
    }
    float ip[4], op[4], up[4];
    {
      float n0 = sqrtf(wdot<4>(ni,ni)+1e-15f);
      float s0 = __fdividef(fatanh(n0), n0);
      float n1 = sqrtf(wdot<4>(ni+4,ni+4)+1e-15f);
      float s1 = __fdividef(fatanh(n1), n1);
      float n2 = sqrtf(wdot<4>(ni+8,ni+8)+1e-15f);
      float s2 = __fdividef(fatanh(n2), n2);
      #pragma unroll
      for(int i=0;i<4;i++){
        ip[i] = fsig(ni[i]*s0);
        op[i] = fsig(ni[4+i]*s1);
        up[i] = ftanh(ni[8+i]*s2);
      }
    }
    float nup = sqrtf(wdot<4>(up,up)+1e-15f);
    float t[4];
    float mt = pwmulp_k(ip, up, nup, t);
    float cc[4]; ld4(cc, g_c1o+b);
    float y2c = g_n2c1o[nd];
    float xys = 0.f;
    #pragma unroll
    for(int i=0;i<4;i++) xys += t[i]*cc[i];
    float xyc = wred(xys);
    float x2c = mt*mt;
    float cxc = 1.f+2.f*xyc+y2c, cyc = 1.f-x2c;
    float idnc = __fdividef(1.f, safe_den(1.f+2.f*xyc+x2c*y2c));
    float nc[4];
    #pragma unroll
    for(int i=0;i<4;i++) nc[i] = (cxc*t[i] + cyc*cc[i])*idnc;
    float n2nc = fmaxf((cxc*cxc*x2c + 2.f*cxc*cyc*xyc + cyc*cyc*y2c)*idnc*idnc, 0.f);
    float nnc = sqrtf(n2nc + 1e-15f);
    if(nnc > PMF){
      float sc = __fdividef(PMF, nnc);
      #pragma unroll
      for(int i=0;i<4;i++) nc[i] *= sc;
      nnc = PMF;
    }
    float lt[4];
    {
      float sc = __fdividef(fatanh(nnc), nnc);
      #pragma unroll
      for(int i=0;i<4;i++) lt[i] = ftanh(nc[i]*sc);
    }
    float nlt = sqrtf(wdot<4>(lt,lt)+1e-15f);
    float nh[4];
    pwmulp_k(op, lt, nlt, nh);
    st4(out + 0*NN*128 + b, nh);
    st4(out + 1*NN*128 + b, nc);
  }

  // ---- Sphere
  {
    float z[12], io[12];
    #pragma unroll
    for(int c=0;c<3;c++){ ld4(z+4*c, g_Z2 + b3 + 128*c); ld4(io+4*c, iou2 + b3 + 128*c); }
    float nz = sqrtf(wdot<12>(z,z)+1e-15f);
    float mz = ftan(nz);
    {
      float sc = __fdividef(mz, nz);
      #pragma unroll
      for(int i=0;i<12;i++) z[i] *= sc;
    }
    float x2 = wdot<12>(io,io);
    float xy = wdot<12>(io,z);
    float y2 = mz*mz;
    float cx = 1.f-2.f*xy-y2, cy = 1.f+x2;
    float idn = __fdividef(1.f, safe_den(1.f-2.f*xy+x2*y2));
    float ni[12];
    #pragma unroll
    for(int i=0;i<12;i++) ni[i] = (cx*io[i] + cy*z[i])*idn;
    float ip[4], op[4], up[4];
    {
      float n0 = sqrtf(wdot<4>(ni,ni)+1e-15f);
      float s0 = __fdividef(atanf(n0), n0);
      float n1 = sqrtf(wdot<4>(ni+4,ni+4)+1e-15f);
      float s1 = __fdividef(atanf(n1), n1);
      float n2 = sqrtf(wdot<4>(ni+8,ni+8)+1e-15f);
      float s2 = __fdividef(atanf(n2), n2);
      #pragma unroll
      for(int i=0;i<4;i++){
        ip[i] = fsig(ni[i]*s0);
        op[i] = fsig(ni[4+i]*s1);
        up[i] = ftanh(ni[8+i]*s2);
      }
    }
    float nup = sqrtf(wdot<4>(up,up)+1e-15f);
    float t[4];
    float mt = pwmuls_k(ip, up, nup, t);
    float cc[4]; ld4(cc, g_c2o+b);
    float y2c = g_n2c2o[nd];
    float xys = 0.f;
    #pragma unroll
    for(int i=0;i<4;i++) xys += t[i]*cc[i];
    float xyc = wred(xys);
    float x2c = mt*mt;
    float cxc = 1.f-2.f*xyc-y2c, cyc = 1.f+x2c;
    float idnc = __fdividef(1.f, safe_den(1.f-2.f*xyc+x2c*y2c));
    float nc[4];
    #pragma unroll
    for(int i=0;i<4;i++) nc[i] = (cxc*t[i] + cyc*cc[i])*idnc;
    float n2nc = fmaxf((cxc*cxc*x2c + 2.f*cxc*cyc*xyc + cyc*cyc*y2c)*idnc*idnc, 0.f);
    float nnc = sqrtf(n2nc + 1e-15f);
    float lt[4];
    {
      float sc = __fdividef(atanf(nnc), nnc);
      #pragma unroll
      for(int i=0;i<4;i++) lt[i] = ftanh(nc[i]*sc);
    }
    float nlt = sqrtf(wdot<4>(lt,lt)+1e-15f);
    float nh[4];
    pwmuls_k(op, lt, nlt, nh);
    st4(out + 2*NN*128 + b, nh);
    st4(out + 3*NN*128 + b, nc);
  }

  // ---- Euclid
  {
    float z[12], io[12];
    #pragma unroll
    for(int c=0;c<3;c++){ ld4(z+4*c, g_Z3 + b3 + 128*c); ld4(io+4*c, iou3 + b3 + 128*c); }
    float cc[4]; ld4(cc, g_c3o+b);
    float nc[4], nh[4];
    #pragma unroll
    for(int i=0;i<4;i++){
      float ip = fsig(io[i]   + z[i]);
      float op = fsig(io[4+i] + z[4+i]);
      float up = ftanh(io[8+i] + z[8+i]);
      nc[i] = ip*up + cc[i];
      nh[i] = op*ftanh(nc[i]);
    }
    st4(out + 4*NN*128 + b, nh);
    st4(out + 5*NN*128 + b, nc);
  }
}

// ----------------------------- launch -----------------------------
extern "C" void kernel_launch(void* const* d_in, const int* in_sizes, int n_in,
                              void* d_out, int out_size){
  const float* x     = (const float*)d_in[0];
  const float* h1    = (const float*)d_in[1];
  const float* c1    = (const float*)d_in[2];
  const float* h2    = (const float*)d_in[3];
  const float* c2    = (const float*)d_in[4];
  const float* h3    = (const float*)d_in[5];
  const float* c3    = (const float*)d_in[6];
  const float* del_t = (const float*)d_in[7];
  const float* iou1  = (const float*)d_in[8];
  const float* iou2  = (const float*)d_in[9];
  const float* iou3  = (const float*)d_in[10];
  const float* Wq_w  = (const float*)d_in[11];
  const float* Wq_b  = (const float*)d_in[12];
  const float* Wc_w  = (const float*)d_in[13];
  const float* Wc_b  = (const float*)d_in[14];
  const float* Uf_w  = (const float*)d_in[15];
  const float* Uf_b  = (const float*)d_in[16];
  const float* Up_w  = (const float*)d_in[17];
  const float* Up_b  = (const float*)d_in[18];
  const float* Uiou_w= (const float*)d_in[19];
  const float* Uiou_b= (const float*)d_in[20];
  const float* dptr  = (const float*)d_in[21];
  const int*   nbr   = (const int*)d_in[22];
  float* out = (float*)d_out;

  cudaFuncSetAttribute(k_gemm1, cudaFuncAttributeMaxDynamicSharedMemorySize, GSMEM);
  cudaFuncSetAttribute(k_gemm2, cudaFuncAttributeMaxDynamicSharedMemorySize, GSMEM);

  k_prep<<<NN/8 + 224, 256>>>(h1, h2, c1, c2, x, h3, c3, Wq_w, Wc_w, Uf_w, Up_w, Uiou_w);
  k_gemm1<<<dim3(NN/64, 1, 10), 256, GSMEM>>>(Wq_b, Wc_b, Uf_b, Up_b);
  k_node<<<dim3(NN/8, 2), 256>>>(h1, h2, h3, c1, c2, c3, del_t, dptr);
  k_attn<<<NN/8, 256>>>(nbr);
  k_gemm2<<<dim3(NN/64, 3, 3), 256, GSMEM>>>(Uiou_b);
  k_final<<<NN/8, 256>>>(iou1, iou2, iou3, out);
}

// round 16
// speedup vs baseline: 1.0638x; 1.0240x over previous
#include <cuda_runtime.h>
#include <cuda_bf16.h>
#include <math.h>
#include <stdint.h>

#define NN 8192
#define HH 128
#define H3 384
#define EPSF 1e-6f
#define PMF 0.9999f
#define PADH 36
#define GSMEM (384 * PADH * 4)

// ----------------------------- fp32 scratch -----------------------------
__device__ float g_Yq[NN*HH];
__device__ float g_Yup1[NN*HH], g_Yup2[NN*HH], g_Yup3[NN*HH];
__device__ float g_Yuf1[NN*HH], g_Yuf2[NN*HH], g_Yuf3[NN*HH];
__device__ float g_Ywc1[NN*HH], g_Ywc2[NN*HH], g_Ywc3[NN*HH];
__device__ float g_h1p[NN*HH], g_h1s[NN*HH], g_h1e[NN*HH];
__device__ float g_P1[NN*HH], g_P2[NN*HH], g_E3[NN*HH];
__device__ float g_c1o[NN*HH], g_c2o[NN*HH], g_c3o[NN*HH];
__device__ float g_Z1[NN*H3], g_Z2[NN*H3], g_Z3[NN*H3];
// per-node scalars
__device__ float g_y2p[NN], g_y2s[NN], g_lam1[NN], g_lam2[NN];
__device__ float g_nh1[NN], g_nh2[NN];
__device__ float g_n2c1o[NN], g_n2c2o[NN];
// bf16 hi/lo packed
__device__ uint32_t g_xh[NN*64],  g_xl[NN*64];
__device__ uint32_t g_l1h[NN*64], g_l1l[NN*64];
__device__ uint32_t g_l2h[NN*64], g_l2l[NN*64];
__device__ uint32_t g_h3h[NN*64], g_h3l[NN*64];
__device__ uint32_t g_lc1h[NN*64], g_lc1l[NN*64];
__device__ uint32_t g_lc2h[NN*64], g_lc2l[NN*64];
__device__ uint32_t g_c3h[NN*64], g_c3l[NN*64];
__device__ uint32_t g_A1h[NN*64], g_A1l[NN*64];
__device__ uint32_t g_A2h[NN*64], g_A2l[NN*64];
__device__ uint32_t g_A3h[NN*64], g_A3l[NN*64];
__device__ uint32_t g_Wqh[128*64], g_Wql[128*64];
__device__ uint32_t g_Wch[128*64], g_Wcl[128*64];
__device__ uint32_t g_Ufh[128*64], g_Ufl[128*64];
__device__ uint32_t g_Uph[128*64], g_Upl[128*64];
__device__ uint32_t g_Uih[384*64], g_Uil[384*64];

// ----------------------------- fast math -----------------------------
__device__ __forceinline__ float ftanh(float x){
  float a = fabsf(x);
  float r;
  if(a < 0.105f){
    float a2 = a*a;
    r = a*(1.f - a2*(0.33333334f - a2*0.13333334f));
  } else {
    float t = __expf(-2.f*a);
    r = __fdividef(1.f - t, 1.f + t);
  }
  return copysignf(r, x);
}
__device__ __forceinline__ float fatanh(float u){
  u = fminf(fmaxf(u, -1.f + 1e-5f), 1.f - 1e-5f);
  float a = fabsf(u);
  float r;
  if(a < 0.105f){
    float a2 = a*a;
    r = a*(1.f + a2*(0.33333334f + a2*0.2f));
  } else {
    r = 0.5f*__logf(__fdividef(1.f + a, 1.f - a));
  }
  return copysignf(r, u);
}
__device__ __forceinline__ float fsig(float x){
  return __fdividef(1.f, 1.f + __expf(-x));
}
__device__ __forceinline__ float ftan(float u){
  u = fminf(fmaxf(u, -1.47079f), 1.47079f);
  return __tanf(u);
}
__device__ __forceinline__ float safe_den(float d){
  return d >= 0.f ? fmaxf(d, EPSF) : fminf(d, -EPSF);
}

// ----------------------------- warp helpers -----------------------------
__device__ __forceinline__ float wred(float s){
  #pragma unroll
  for(int o=16;o;o>>=1) s += __shfl_xor_sync(0xffffffffu, s, o);
  return s;
}
template<int R> __device__ __forceinline__ float wdot(const float* a, const float* b){
  float s=0.f;
  #pragma unroll
  for(int i=0;i<R;i++) s += a[i]*b[i];
  return wred(s);
}
__device__ __forceinline__ void ld4(float* v, const float* p){
  float4 t = *(const float4*)p; v[0]=t.x; v[1]=t.y; v[2]=t.z; v[3]=t.w;
}
__device__ __forceinline__ void st4(float* p, const float* v){
  *(float4*)p = make_float4(v[0],v[1],v[2],v[3]);
}

__device__ __forceinline__ float pwmulp_k(const float* w, const float* x, float nx, float* o){
  float wx[4];
  #pragma unroll
  for(int i=0;i<4;i++) wx[i] = w[i]*x[i];
  float nwx = sqrtf(wdot<4>(wx,wx) + 1e-15f);
  float m = fminf(ftanh(__fdividef(nwx,nx)*fatanh(nx)), PMF);
  float s = __fdividef(m, nwx);
  #pragma unroll
  for(int i=0;i<4;i++) o[i] = wx[i]*s;
  return m;
}
__device__ __forceinline__ float pwmuls_k(const float* w, const float* x, float nx, float* o){
  float wx[4];
  #pragma unroll
  for(int i=0;i<4;i++) wx[i] = w[i]*x[i];
  float nwx = sqrtf(wdot<4>(wx,wx) + 1e-15f);
  float m = ftan(__fdividef(nwx,nx)*atanf(nx));
  float s = __fdividef(m, nwx);
  #pragma unroll
  for(int i=0;i<4;i++) o[i] = wx[i]*s;
  return m;
}

// ----------------------------- bf16 packing -----------------------------
__device__ __forceinline__ uint32_t pack_bf2(float f0, float f1){
  __nv_bfloat16 b0 = __float2bfloat16_rn(f0);
  __nv_bfloat16 b1 = __float2bfloat16_rn(f1);
  return ((uint32_t)__bfloat16_as_ushort(b1)<<16) | (uint32_t)__bfloat16_as_ushort(b0);
}
__device__ __forceinline__ void split_bf2(float f0, float f1, uint32_t& hi, uint32_t& lo){
  __nv_bfloat16 b0 = __float2bfloat16_rn(f0);
  __nv_bfloat16 b1 = __float2bfloat16_rn(f1);
  hi = ((uint32_t)__bfloat16_as_ushort(b1)<<16) | (uint32_t)__bfloat16_as_ushort(b0);
  lo = pack_bf2(f0 - __bfloat162float(b0), f1 - __bfloat162float(b1));
}
__device__ __forceinline__ void pack_store(uint32_t* dh, uint32_t* dl, int idx, const float* v){
  uint32_t h0,l0,h1,l1;
  split_bf2(v[0],v[1],h0,l0);
  split_bf2(v[2],v[3],h1,l1);
  *(uint2*)(dh+idx) = make_uint2(h0,h1);
  *(uint2*)(dl+idx) = make_uint2(l0,l1);
}

// ----------------------------- GEMM (bf16 3-term, ldmatrix, K-split) -----------------------------
__device__ __forceinline__ void mma16(float* d, const uint32_t* a, const uint32_t* b){
  asm volatile("mma.sync.aligned.m16n8k16.row.col.f32.bf16.bf16.f32 "
    "{%0,%1,%2,%3},{%4,%5,%6,%7},{%8,%9},{%0,%1,%2,%3};"
    : "+f"(d[0]),"+f"(d[1]),"+f"(d[2]),"+f"(d[3])
    : "r"(a[0]),"r"(a[1]),"r"(a[2]),"r"(a[3]),"r"(b[0]),"r"(b[1]));
}
__device__ __forceinline__ void ldsm4(uint32_t& r0, uint32_t& r1, uint32_t& r2, uint32_t& r3, uint32_t addr){
  asm volatile("ldmatrix.sync.aligned.m8n8.x4.shared.b16 {%0,%1,%2,%3}, [%4];"
    : "=r"(r0),"=r"(r1),"=r"(r2),"=r"(r3) : "r"(addr));
}

__device__ __forceinline__ void gemm_pk(const uint32_t* __restrict__ AhG, const uint32_t* __restrict__ AlG,
                                        const uint32_t* __restrict__ BhG, const uint32_t* __restrict__ BlG,
                                        const float* __restrict__ bias, float* __restrict__ C, int HO){
  extern __shared__ uint32_t sh[];
  uint32_t* Ah = sh;
  uint32_t* Al = sh + 64*PADH;
  uint32_t* Bh = sh + 128*PADH;
  uint32_t* Bl = sh + 256*PADH;
  const int m0 = blockIdx.x*64;
  const int n0 = blockIdx.y*128;
  const int t = threadIdx.x;
  const int lane = t & 31, w = t >> 5;
  const int wm = w >> 2, wn = w & 3;
  const int gid = lane >> 2, tig = lane & 3;

  uint32_t shbase = (uint32_t)__cvta_generic_to_shared(sh);
  int rowA = wm*32 + (lane & 15);
  int colA = ((lane >> 4) & 1) * 4;
  uint32_t aAh0 = shbase + (uint32_t)((rowA*PADH + colA) * 4);
  uint32_t aAh1 = aAh0 + 16u*PADH*4u;
  uint32_t aAl0 = aAh0 + 64u*PADH*4u;
  uint32_t aAl1 = aAh1 + 64u*PADH*4u;
  int rowB = wn*32 + ((lane >> 4) & 1) * 8 + (lane & 7);
  int colB = ((lane >> 3) & 1) * 4;
  uint32_t aBh0 = shbase + (uint32_t)((128*PADH + rowB*PADH + colB) * 4);
  uint32_t aBh1 = aBh0 + 16u*PADH*4u;
  uint32_t aBl0 = aBh0 + 128u*PADH*4u;
  uint32_t aBl1 = aBh1 + 128u*PADH*4u;

  float acc[2][4][4];
  #pragma unroll
  for(int mt=0;mt<2;mt++)
    #pragma unroll
    for(int nt=0;nt<4;nt++)
      #pragma unroll
      for(int i=0;i<4;i++) acc[mt][nt][i]=0.f;

  #pragma unroll
  for(int half=0; half<2; half++){
    int c0 = half*32;
    if(half) __syncthreads();
    #pragma unroll
    for(int i=0;i<2;i++){
      int p = t + i*256; int r = p>>3, c = (p&7)*4;
      *(uint4*)(Ah + r*PADH + c) = *(const uint4*)(AhG + (m0+r)*64 + c0 + c);
      *(uint4*)(Al + r*PADH + c) = *(const uint4*)(AlG + (m0+r)*64 + c0 + c);
    }
    #pragma unroll
    for(int i=0;i<4;i++){
      int p = t + i*256; int r = p>>3, c = (p&7)*4;
      *(uint4*)(Bh + r*PADH + c) = *(const uint4*)(BhG + (n0+r)*64 + c0 + c);
      *(uint4*)(Bl + r*PADH + c) = *(const uint4*)(BlG + (n0+r)*64 + c0 + c);
    }
    __syncthreads();
    #pragma unroll
    for(int s=0;s<4;s++){
      uint32_t ko = (uint32_t)(s*8*4);
      uint32_t ah[2][4], al[2][4], bh[4][2], bl[4][2];
      ldsm4(ah[0][0], ah[0][1], ah[0][2], ah[0][3], aAh0 + ko);
      ldsm4(ah[1][0], ah[1][1], ah[1][2], ah[1][3], aAh1 + ko);
      ldsm4(al[0][0], al[0][1], al[0][2], al[0][3], aAl0 + ko);
      ldsm4(al[1][0], al[1][1], al[1][2], al[1][3], aAl1 + ko);
      ldsm4(bh[0][0], bh[0][1], bh[1][0], bh[1][1], aBh0 + ko);
      ldsm4(bh[2][0], bh[2][1], bh[3][0], bh[3][1], aBh1 + ko);
      ldsm4(bl[0][0], bl[0][1], bl[1][0], bl[1][1], aBl0 + ko);
      ldsm4(bl[2][0], bl[2][1], bl[3][0], bl[3][1], aBl1 + ko);
      #pragma unroll
      for(int mt=0;mt<2;mt++)
        #pragma unroll
        for(int nt=0;nt<4;nt++){
          mma16(acc[mt][nt], al[mt], bh[nt]);
          mma16(acc[mt][nt], ah[mt], bl[nt]);
          mma16(acc[mt][nt], ah[mt], bh[nt]);
        }
    }
  }

  #pragma unroll
  for(int mt=0;mt<2;mt++){
    int r = m0 + wm*32 + mt*16 + gid;
    #pragma unroll
    for(int nt=0;nt<4;nt++){
      int c = n0 + wn*32 + nt*8 + tig*2;
      float b0 = bias[c], b1 = bias[c+1];
      *(float2*)(C + r*HO + c)     = make_float2(acc[mt][nt][0]+b0, acc[mt][nt][1]+b1);
      *(float2*)(C + (r+8)*HO + c) = make_float2(acc[mt][nt][2]+b0, acc[mt][nt][3]+b1);
    }
  }
}

__global__ void __launch_bounds__(256) k_gemm1(const float* __restrict__ bq, const float* __restrict__ bc,
                                               const float* __restrict__ bf, const float* __restrict__ bp){
  const uint32_t *Ah,*Al,*Bh,*Bl; const float* B; float* C;
  switch(blockIdx.z){
    case 0: Ah=g_xh;  Al=g_xl;  Bh=g_Wqh; Bl=g_Wql; B=bq; C=g_Yq;   break;
    case 1: Ah=g_l1h; Al=g_l1l; Bh=g_Uph; Bl=g_Upl; B=bp; C=g_Yup1; break;
    case 2: Ah=g_l2h; Al=g_l2l; Bh=g_Uph; Bl=g_Upl; B=bp; C=g_Yup2; break;
    case 3: Ah=g_h3h; Al=g_h3l; Bh=g_Uph; Bl=g_Upl; B=bp; C=g_Yup3; break;
    case 4: Ah=g_l1h; Al=g_l1l; Bh=g_Ufh; Bl=g_Ufl; B=bf; C=g_Yuf1; break;
    case 5: Ah=g_l2h; Al=g_l2l; Bh=g_Ufh; Bl=g_Ufl; B=bf; C=g_Yuf2; break;
    case 6: Ah=g_h3h; Al=g_h3l; Bh=g_Ufh; Bl=g_Ufl; B=bf; C=g_Yuf3; break;
    case 7: Ah=g_lc1h;Al=g_lc1l;Bh=g_Wch; Bl=g_Wcl; B=bc; C=g_Ywc1; break;
    case 8: Ah=g_lc2h;Al=g_lc2l;Bh=g_Wch; Bl=g_Wcl; B=bc; C=g_Ywc2; break;
    default:Ah=g_c3h; Al=g_c3l; Bh=g_Wch; Bl=g_Wcl; B=bc; C=g_Ywc3; break;
  }
  gemm_pk(Ah, Al, Bh, Bl, B, C, 128);
}

__global__ void __launch_bounds__(256) k_gemm2(const float* __restrict__ bi){
  const uint32_t *Ah,*Al; float* C;
  switch(blockIdx.z){
    case 0: Ah=g_A1h; Al=g_A1l; C=g_Z1; break;
    case 1: Ah=g_A2h; Al=g_A2l; C=g_Z2; break;
    default:Ah=g_A3h; Al=g_A3l; C=g_Z3; break;
  }
  gemm_pk(Ah, Al, g_Uih, g_Uil, bi, C, 384);
}

// ----------------------------- prep -----------------------------
__global__ void k_prep(const float* __restrict__ h1, const float* __restrict__ h2,
                       const float* __restrict__ c1, const float* __restrict__ c2,
                       const float* __restrict__ x,  const float* __restrict__ h3,
                       const float* __restrict__ c3,
                       const float* __restrict__ Wq, const float* __restrict__ Wc,
                       const float* __restrict__ Uf, const float* __restrict__ Up,
                       const float* __restrict__ Ui){
  if(blockIdx.x >= NN/8){
    int i = (blockIdx.x - NN/8)*256 + threadIdx.x;
    const float* src; uint32_t *dh, *dl; int off;
    if(i < 8192){ src=Wq; dh=g_Wqh; dl=g_Wql; off=i; }
    else if(i < 16384){ src=Wc; dh=g_Wch; dl=g_Wcl; off=i-8192; }
    else if(i < 24576){ src=Uf; dh=g_Ufh; dl=g_Ufl; off=i-16384; }
    else if(i < 32768){ src=Up; dh=g_Uph; dl=g_Upl; off=i-24576; }
    else if(i < 57344){ src=Ui; dh=g_Uih; dl=g_Uil; off=i-32768; }
    else return;
    float2 v = *(const float2*)(src + off*2);
    uint32_t hi, lo; split_bf2(v.x, v.y, hi, lo);
    dh[off]=hi; dl[off]=lo;
    return;
  }
  int nd = (blockIdx.x*blockDim.x + threadIdx.x) >> 5;
  int l = threadIdx.x & 31;
  int b = nd*128 + l*4;
  int bi = nd*64 + l*2;
  float v[4], w[4];
  ld4(v, h1+b);
  float nr = sqrtf(wdot<4>(v,v) + 1e-15f);
  float s = __fdividef(fatanh(nr), nr);
  #pragma unroll
  for(int i=0;i<4;i++) w[i]=v[i]*s;
  pack_store(g_l1h,g_l1l,bi,w);
  if(l==0) g_nh1[nd] = nr;
  ld4(v, h2+b);
  nr = sqrtf(wdot<4>(v,v) + 1e-15f);
  s = __fdividef(atanf(nr), nr);
  #pragma unroll
  for(int i=0;i<4;i++) w[i]=v[i]*s;
  pack_store(g_l2h,g_l2l,bi,w);
  if(l==0) g_nh2[nd] = nr;
  ld4(v, c1+b);
  nr = sqrtf(wdot<4>(v,v) + 1e-15f);
  s = __fdividef(fatanh(nr), nr);
  #pragma unroll
  for(int i=0;i<4;i++) w[i]=v[i]*s;
  pack_store(g_lc1h,g_lc1l,bi,w);
  ld4(v, c2+b);
  nr = sqrtf(wdot<4>(v,v) + 1e-15f);
  s = __fdividef(atanf(nr), nr);
  #pragma unroll
  for(int i=0;i<4;i++) w[i]=v[i]*s;
  pack_store(g_lc2h,g_lc2l,bi,w);
  ld4(v, x+b);  pack_store(g_xh, g_xl, bi, v);
  ld4(v, h3+b); pack_store(g_h3h,g_h3l,bi, v);
  ld4(v, c3+b); pack_store(g_c3h,g_c3l,bi, v);
}

// ----------------------------- per-node elementwise (split 2-way, reg-capped) -----------------------------
__global__ void __launch_bounds__(256, 4) k_node(const float* __restrict__ h1, const float* __restrict__ h2,
                       const float* __restrict__ h3, const float* __restrict__ c1,
                       const float* __restrict__ c2, const float* __restrict__ c3,
                       const float* __restrict__ del_t, const float* __restrict__ dptr){
  int nd = (blockIdx.x*blockDim.x + threadIdx.x) >> 5;
  if(nd >= NN) return;
  int l = threadIdx.x & 31;
  int b = nd*128 + l*4;

  if(blockIdx.y == 0){
    float s1[4];
    {
      ld4(s1, g_Yup1+b);
      float nt = sqrtf(wdot<4>(s1,s1)+1e-15f);
      float me = fminf(ftanh(nt), PMF);
      float sc = __fdividef(me, nt);
      #pragma unroll
      for(int i=0;i<4;i++) s1[i] = fsig(s1[i]*sc);
      float ns = sqrtf(wdot<4>(s1,s1)+1e-15f);
      float sl = __fdividef(fatanh(ns), ns);
      #pragma unroll
      for(int i=0;i<4;i++) s1[i] *= sl;
    }
    float s2[4];
    {
      ld4(s2, g_Yup2+b);
      float nt = sqrtf(wdot<4>(s2,s2)+1e-15f);
      float me = ftan(nt);
      float sc = __fdividef(me, nt);
      #pragma unroll
      for(int i=0;i<4;i++) s2[i] = fsig(s2[i]*sc);
      float ns = sqrtf(wdot<4>(s2,s2)+1e-15f);
      float sl = __fdividef(atanf(ns), ns);
      #pragma unroll
      for(int i=0;i<4;i++) s2[i] *= sl;
    }
    float s3[4]; ld4(s3, g_Yup3+b);
    #pragma unroll
    for(int i=0;i<4;i++) s3[i] = fsig(s3[i]);

    float h1v[4],h2v[4],h3v[4];
    ld4(h1v, h1+b); ld4(h2v, h2+b); ld4(h3v, h3+b);
    float nh1 = g_nh1[nd], nh2 = g_nh2[nd];
    float nh3 = sqrtf(wdot<4>(h3v,h3v)+1e-15f);

    float ht1p[4], ht2p[4], ht3p[4], tmp[4];
    float m1p = pwmulp_k(s1, h1v, nh1, ht1p);
    float m2p, m3p;
    {
      float mm = fminf(ftanh(atanf(nh2)), PMF);
      float sc = __fdividef(mm, nh2);
      #pragma unroll
      for(int i=0;i<4;i++) tmp[i] = h2v[i]*sc;
      m2p = pwmulp_k(s2, tmp, mm, ht2p);
    }
    {
      float mm = fminf(ftanh(nh3), PMF);
      float sc = __fdividef(mm, nh3);
      #pragma unroll
      for(int i=0;i<4;i++) tmp[i] = h3v[i]*sc;
      m3p = pwmulp_k(s3, tmp, mm, ht3p);
    }
    {
      float la = __fdividef(2.f, 1.f-m1p*m1p);
      float lb = __fdividef(2.f, 1.f-m2p*m2p);
      float lc = __fdividef(2.f, 1.f-m3p*m3p);
      float den = fmaxf(fabsf(la+lb+lc-3.f), EPSF);
      float num[4];
      #pragma unroll
      for(int i=0;i<4;i++) num[i] = la*ht1p[i]+lb*ht2p[i]+lc*ht3p[i];
      float nnum = sqrtf(wdot<4>(num,num)+1e-15f);
      float nn = __fdividef(nnum, den);
      float m = fminf(ftanh(0.5f*fatanh(nn)), PMF);
      float sc = __fdividef(3.f*m, nnum);
      #pragma unroll
      for(int i=0;i<4;i++) num[i] *= sc;
      st4(g_h1p+b, num);
      if(l==0) g_y2p[nd] = 9.f*m*m;
    }

    float ht1s[4], ht2s[4], ht3s[4];
    float m2s;
    {
      float nl1 = fatanh(nh1);
      float mm = ftan(nl1);
      float sc = __fdividef(mm, nh1);
      #pragma unroll
      for(int i=0;i<4;i++) tmp[i] = h1v[i]*sc;
      float m1s = pwmulp_k(s1, tmp, mm, ht1s);
      m2s = pwmuls_k(s2, h2v, nh2, ht2s);
      float mm3 = ftan(nh3);
      float sc3 = __fdividef(mm3, nh3);
      #pragma unroll
      for(int i=0;i<4;i++) tmp[i] = h3v[i]*sc3;
      float m3s = pwmuls_k(s3, tmp, mm3, ht3s);
      float la = __fdividef(2.f, 1.f-m1s*m1s);
      float lb = __fdividef(2.f, 1.f-m2s*m2s);
      float lc = __fdividef(2.f, 1.f-m3s*m3s);
      float den = fmaxf(fabsf(la+lb+lc-3.f), EPSF);
      float num[4];
      #pragma unroll
      for(int i=0;i<4;i++) num[i] = la*ht1s[i]+lb*ht2s[i]+lc*ht3s[i];
      float nnum = sqrtf(wdot<4>(num,num)+1e-15f);
      float nn = __fdividef(nnum, den);
      float m = fminf(ftanh(0.5f*fatanh(nn)), PMF);
      float sc2 = __fdividef(3.f*m, nnum);
      #pragma unroll
      for(int i=0;i<4;i++) num[i] *= sc2;
      st4(g_h1s+b, num);
      if(l==0) g_y2s[nd] = 9.f*m*m;
    }

    {
      float e1s = __fdividef(fatanh(m1p), m1p);
      float e2s = __fdividef(atanf(m2s), m2s);
      float he[4];
      #pragma unroll
      for(int i=0;i<4;i++) he[i] = ht1p[i]*e1s + ht2s[i]*e2s + s3[i]*h3v[i];
      st4(g_h1e+b, he);
    }
  } else {
    float g = __fdividef(dptr[0], del_t[nd] + 1.f);
    float nx2 = sqrtf(g*g + 1e-15f);
    float ax2 = fatanh(nx2);
    float sx2 = atanf(nx2);

    // Poincare cell
    {
      float c1v[4]; ld4(c1v, c1+b);
      float cw[4]; ld4(cw, g_Ywc1+b);
      float nw = sqrtf(wdot<4>(cw,cw)+1e-15f);
      {
        float sc = __fdividef(fatanh(fminf(ftanh(nw),PMF)), nw);
        #pragma unroll
        for(int i=0;i<4;i++) cw[i] = ftanh(cw[i]*sc);
      }
      float nck = sqrtf(wdot<4>(cw,cw)+1e-15f);
      float mk = fminf(ftanh(nck), PMF);
      {
        float sc = __fdividef(mk, nck);
        #pragma unroll
        for(int i=0;i<4;i++) cw[i] *= sc;
      }
      float x2 = mk*mk;
      float y2 = wdot<4>(c1v,c1v);
      float xys = 0.f;
      #pragma unroll
      for(int i=0;i<4;i++) xys -= cw[i]*c1v[i];
      float xy = wred(xys);
      float cx = 1.f+2.f*xy+y2, cy = 1.f-x2;
      float idn = __fdividef(1.f, safe_den(1.f+2.f*xy+x2*y2));
      float t1[4];
      #pragma unroll
      for(int i=0;i<4;i++) t1[i] = (cx*(-cw[i]) + cy*c1v[i])*idn;
      float n2t1 = fmaxf((cx*cx*x2 + 2.f*cx*cy*xy + cy*cy*y2)*idn*idn, 0.f);
      if(n2t1 > PMF*PMF){
        float sc = PMF*rsqrtf(n2t1);
        #pragma unroll
        for(int i=0;i<4;i++) t1[i] *= sc;
        n2t1 = PMF*PMF;
      }
      float m2 = fminf(ftanh(__fdividef(g*mk, nx2)*ax2), PMF);
      float t2s = __fdividef(m2, mk);
      float xys2 = 0.f;
      #pragma unroll
      for(int i=0;i<4;i++) xys2 += t1[i]*cw[i]*t2s;
      float xy2 = wred(xys2);
      x2 = n2t1; y2 = m2*m2;
      cx = 1.f+2.f*xy2+y2; cy = 1.f-x2;
      idn = __fdividef(1.f, safe_den(1.f+2.f*xy2+x2*y2));
      float ck[4];
      #pragma unroll
      for(int i=0;i<4;i++) ck[i] = (cx*t1[i] + cy*cw[i]*t2s)*idn;
      float n2ck = fmaxf((cx*cx*x2 + 2.f*cx*cy*xy2 + cy*cy*y2)*idn*idn, 0.f);
      float nckt = sqrtf(n2ck + 1e-15f);
      if(nckt > PMF){
        float sc = __fdividef(PMF, nckt);
        #pragma unroll
        for(int i=0;i<4;i++) ck[i] *= sc;
        nckt = PMF;
      }
      float fp[4]; ld4(fp, g_Yuf1+b);
      float nf = sqrtf(wdot<4>(fp,fp)+1e-15f);
      float scf = __fdividef(fatanh(fminf(ftanh(nf),PMF)), nf);
      #pragma unroll
      for(int i=0;i<4;i++) fp[i] = fsig(fp[i]*scf);
      float P1[4];
      float mP1 = pwmulp_k(fp, ck, nckt, P1);
      st4(g_P1+b, P1);
      if(l==0) g_lam1[nd] = __fdividef(2.f, 1.f-mP1*mP1);
    }

    // Sphere cell
    {
      float c2v[4]; ld4(c2v, c2+b);
      float cw[4]; ld4(cw, g_Ywc2+b);
      float nw = sqrtf(wdot<4>(cw,cw)+1e-15f);
      {
        float sc = __fdividef(atanf(ftan(nw)), nw);
        #pragma unroll
        for(int i=0;i<4;i++) cw[i] = ftanh(cw[i]*sc);
      }
      float nck = sqrtf(wdot<4>(cw,cw)+1e-15f);
      float mk = ftan(nck);
      {
        float sc = __fdividef(mk, nck);
        #pragma unroll
        for(int i=0;i<4;i++) cw[i] *= sc;
      }
      float x2 = mk*mk;
      float y2 = wdot<4>(c2v,c2v);
      float xys = 0.f;
      #pragma unroll
      for(int i=0;i<4;i++) xys -= cw[i]*c2v[i];
      float xy = wred(xys);
      float cx = 1.f-2.f*xy-y2, cy = 1.f+x2;
      float idn = __fdividef(1.f, safe_den(1.f-2.f*xy+x2*y2));
      float t1[4];
      #pragma unroll
      for(int i=0;i<4;i++) t1[i] = (cx*(-cw[i]) + cy*c2v[i])*idn;
      float n2t1 = fmaxf((cx*cx*x2 + 2.f*cx*cy*xy + cy*cy*y2)*idn*idn, 0.f);
      float m2 = ftan(__fdividef(g*mk, nx2)*sx2);
      float t2s = __fdividef(m2, mk);
      float xys2 = 0.f;
      #pragma unroll
      for(int i=0;i<4;i++) xys2 += t1[i]*cw[i]*t2s;
      float xy2 = wred(xys2);
      x2 = n2t1; y2 = m2*m2;
      cx = 1.f-2.f*xy2-y2; cy = 1.f+x2;
      idn = __fdividef(1.f, safe_den(1.f-2.f*xy2+x2*y2));
      float ck[4];
      #pragma unroll
      for(int i=0;i<4;i++) ck[i] = (cx*t1[i] + cy*cw[i]*t2s)*idn;
      float n2ck = fmaxf((cx*cx*x2 + 2.f*cx*cy*xy2 + cy*cy*y2)*idn*idn, 0.f);
      float nckt = sqrtf(n2ck + 1e-15f);
      float fs[4]; ld4(fs, g_Yuf2+b);
      float nf = sqrtf(wdot<4>(fs,fs)+1e-15f);
      float scf = __fdividef(atanf(ftan(nf)), nf);
      #pragma unroll
      for(int i=0;i<4;i++) fs[i] = fsig(fs[i]*scf);
      float P2[4];
      float mP2 = pwmuls_k(fs, ck, nckt, P2);
      st4(g_P2+b, P2);
      if(l==0) g_lam2[nd] = __fdividef(2.f, 1.f+mP2*mP2);
    }

    // Euclid cell
    {
      float c3v[4]; ld4(c3v, c3+b);
      float cske[4]; ld4(cske, g_Ywc3+b);
      float fe[4]; ld4(fe, g_Yuf3+b);
      float E3[4];
      #pragma unroll
      for(int i=0;i<4;i++){
        float ck = ftanh(cske[i]);
        E3[i] = fsig(fe[i])*(c3v[i] - ck + ck*g);
      }
      st4(g_E3+b, E3);
    }
  }
}

// ----------------------------- gather + attention + cells (single-pass softmax) -----------------------------
__global__ void __launch_bounds__(256, 4) k_attn(const int* __restrict__ nbr){
  int nd = (blockIdx.x*blockDim.x + threadIdx.x) >> 5;
  if(nd >= NN) return;
  int l = threadIdx.x & 31;
  int b = nd*128 + l*4;
  int bi = nd*64 + l*2;
  const int* nb = nbr + nd*8;
  int j8[8];
  #pragma unroll
  for(int k=0;k<8;k++) j8[k] = nb[k];

  float yq[4]; ld4(yq, g_Yq+b);
  float nq = sqrtf(wdot<4>(yq,yq) + 1e-15f);

  // ===== Section 1: Poincare attention (single pass, unnormalized softmax) =====
  {
    float mp = fminf(ftanh(nq), PMF);
    float x2 = mp*mp;
    float xq[4];
    float sp = __fdividef(mp, nq);
    #pragma unroll
    for(int i=0;i<4;i++) xq[i] = yq[i]*sp;
    float num[4] = {0,0,0,0};
    float ds = 0.f, se = 0.f;
    #pragma unroll
    for(int k=0;k<8;k++){
      float hk[4]; ld4(hk, g_h1p + j8[k]*128 + l*4);
      float y2 = g_y2p[j8[k]];
      float s = 0.f;
      #pragma unroll
      for(int i=0;i<4;i++) s -= xq[i]*hk[i];
      float xy = wred(s);
      float cx = 1.f + 2.f*xy + y2;
      float cy = 1.f - x2;
      float dn = safe_den(1.f + 2.f*xy + x2*y2);
      float o2 = cx*cx*x2 + 2.f*cx*cy*xy + cy*cy*y2;
      float nr = fminf(__fdividef(sqrtf(fmaxf(o2,0.f) + 1e-15f), fabsf(dn)), PMF);
      float e = __expf(-2.f*fatanh(nr));
      float lam = __fdividef(2.f, 1.f - y2);
      float wk = e*lam;
      #pragma unroll
      for(int i=0;i<4;i++) num[i] += wk*hk[i];
      ds += e*(lam - 1.f);
      se += e;
    }
    float den = fmaxf(fabsf(ds), EPSF*se);
    float nnum = sqrtf(wdot<4>(num,num) + 1e-15f);
    float nn = __fdividef(nnum, den);
    float m = fminf(ftanh(0.5f*fatanh(nn)), PMF);
    float st = __fdividef(fatanh(m), nnum);
    #pragma unroll
    for(int i=0;i<4;i++) num[i] *= st;
    pack_store(g_A1h, g_A1l, bi, num);
  }

  // ===== Section 2: Sphere attention (single pass) =====
  {
    float msp = ftan(nq);
    float x2 = msp*msp;
    float xq[4];
    float ss = __fdividef(msp, nq);
    #pragma unroll
    for(int i=0;i<4;i++) xq[i] = yq[i]*ss;
    float num[4] = {0,0,0,0};
    float ds = 0.f, se = 0.f;
    #pragma unroll
    for(int k=0;k<8;k++){
      float hk[4]; ld4(hk, g_h1s + j8[k]*128 + l*4);
      float y2 = g_y2s[j8[k]];
      float s = 0.f;
      #pragma unroll
      for(int i=0;i<4;i++) s -= xq[i]*hk[i];
      float xy = wred(s);
      float cx = 1.f - 2.f*xy - y2;
      float cy = 1.f + x2;
      float dn = safe_den(1.f - 2.f*xy + x2*y2);
      float o2 = cx*cx*x2 + 2.f*cx*cy*xy + cy*cy*y2;
      float nr = __fdividef(sqrtf(fmaxf(o2,0.f) + 1e-15f), fabsf(dn));
      float e = __expf(-2.f*atanf(nr));
      float lam = __fdividef(2.f, 1.f + y2);
      float wk = e*lam;
      #pragma unroll
      for(int i=0;i<4;i++) num[i] += wk*hk[i];
      ds += e*(lam - 1.f);
      se += e;
    }
    float den = fmaxf(fabsf(ds), EPSF*se);
    float nnum = sqrtf(wdot<4>(num,num) + 1e-15f);
    float nn = __fdividef(nnum, den);
    float m = ftan(0.5f*atanf(nn));
    float st = __fdividef(atanf(m), nnum);
    #pragma unroll
    for(int i=0;i<4;i++) num[i] *= st;
    pack_store(g_A2h, g_A2l, bi, num);
  }

  // ===== Section 3: Euclid attention (single pass) =====
  {
    const float isq = 0.08838834764831845f;
    float num[4] = {0,0,0,0};
    float se = 0.f;
    #pragma unroll
    for(int k=0;k<8;k++){
      float hk[4]; ld4(hk, g_h1e + j8[k]*128 + l*4);
      float s = 0.f;
      #pragma unroll
      for(int i=0;i<4;i++) s += hk[i]*yq[i];
      float e = __expf(wred(s)*isq);
      #pragma unroll
      for(int i=0;i<4;i++) num[i] += e*hk[i];
      se += e;
    }
    float inv = __fdividef(1.f, se);
    #pragma unroll
    for(int i=0;i<4;i++) num[i] *= inv;
    pack_store(g_A3h, g_A3l, bi, num);
  }

  // ===== Section 4: cell reductions (batched) =====
  {
    float c1[4]={0,0,0,0}, c2[4]={0,0,0,0}, c3[4]={0,0,0,0};
    float d1=0.f, d2=0.f;
    #pragma unroll
    for(int k=0;k<8;k++){
      int o = j8[k]*128 + l*4;
      float p1[4], p2[4], e3[4];
      ld4(p1, g_P1 + o); ld4(p2, g_P2 + o); ld4(e3, g_E3 + o);
      float lam1 = g_lam1[j8[k]], lam2 = g_lam2[j8[k]];
      #pragma unroll
      for(int i=0;i<4;i++){ c1[i] += lam1*p1[i]; c2[i] += lam2*p2[i]; c3[i] += e3[i]; }
      d1 += lam1 - 1.f;
      d2 += lam2 - 1.f;
    }
    {
      float den = fmaxf(fabsf(d1), EPSF);
      float nnum = sqrtf(wdot<4>(c1,c1) + 1e-15f);
      float nn = __fdividef(nnum, den);
      float m = fminf(ftanh(0.5f*fatanh(nn)), PMF);
      float st = __fdividef(m, nnum);
      #pragma unroll
      for(int i=0;i<4;i++) c1[i] *= st;
      st4(g_c1o+b, c1);
      if(l==0) g_n2c1o[nd] = m*m;
    }
    {
      float den = fmaxf(fabsf(d2), EPSF);
      float nnum = sqrtf(wdot<4>(c2,c2) + 1e-15f);
      float nn = __fdividef(nnum, den);
      float m = ftan(0.5f*atanf(nn));
      float st = __fdividef(m, nnum);
      #pragma unroll
      for(int i=0;i<4;i++) c2[i] *= st;
      st4(g_c2o+b, c2);
      if(l==0) g_n2c2o[nd] = m*m;
    }
    st4(g_c3o+b, c3);
  }
}

// ----------------------------- final epilogue (reg-capped) -----------------------------
__global__ void __launch_bounds__(256, 3) k_final(const float* __restrict__ iou1, const float* __restrict__ iou2,
                        const float* __restrict__ iou3, float* __restrict__ out){
  int nd = (blockIdx.x*blockDim.x + threadIdx.x) >> 5;
  if(nd >= NN) return;
  int l = threadIdx.x & 31;
  int b = nd*128 + l*4;
  int b3 = nd*384 + l*4;

  // ---- Poincare
  {
    float z[12], io[12];
    #pragma unroll
    for(int c=0;c<3;c++){ ld4(z+4*c, g_Z1 + b3 + 128*c); ld4(io+4*c, iou1 + b3 + 128*c); }
    float nz = sqrtf(wdot<12>(z,z)+1e-15f);
    float mz = fminf(ftanh(nz), PMF);
    {
      float sc = __fdividef(mz, nz);
      #pragma unroll
      for(int i=0;i<12;i++) z[i] *= sc;
    }
    float x2 = wdot<12>(io,io);
    float xy = wdot<12>(io,z);
    float y2 = mz*mz;
    float cx = 1.f+2.f*xy+y2, cy = 1.f-x2;
    float idn = __fdividef(1.f, safe_den(1.f+2.f*xy+x2*y2));
    float ni[12];
    #pragma unroll
    for(int i=0;i<12;i++) ni[i] = (cx*io[i] + cy*z[i])*idn;
    float n2ni = fmaxf((cx*cx*x2 + 2.f*cx*cy*xy + cy*cy*y2)*idn*idn, 0.f);
    if(n2ni > PMF*PMF){
      float sc = PMF*rsqrtf(n2ni);
      #pragma unroll
      for(int i=0;i<12;i++) ni[i] *= sc;
    }
    float ip[4], op[4], up[4];
    {
      float n0 = sqrtf(wdot<4>(ni,ni)+1e-15f);
      float s0 = __fdividef(fatanh(n0), n0);
      float n1 = sqrtf(wdot<4>(ni+4,ni+4)+1e-15f);
      float s1 = __fdividef(fatanh(n1), n1);
      float n2 = sqrtf(wdot<4>(ni+8,ni+8)+1e-15f);
      float s2 = __fdividef(fatanh(n2), n2);
      #pragma unroll
      for(int i=0;i<4;i++){
        ip[i] = fsig(ni[i]*s0);
        op[i] = fsig(ni[4+i]*s1);
        up[i] = ftanh(ni[8+i]*s2);
      }
    }
    float nup = sqrtf(wdot<4>(up,up)+1e-15f);
    float t[4];
    float mt = pwmulp_k(ip, up, nup, t);
    float cc[4]; ld4(cc, g_c1o+b);
    float y2c = g_n2c1o[nd];
    float xys = 0.f;
    #pragma unroll
    for(int i=0;i<4;i++) xys += t[i]*cc[i];
    float xyc = wred(xys);
    float x2c = mt*mt;
    float cxc = 1.f+2.f*xyc+y2c, cyc = 1.f-x2c;
    float idnc = __fdividef(1.f, safe_den(1.f+2.f*xyc+x2c*y2c));
    float nc[4];
    #pragma unroll
    for(int i=0;i<4;i++) nc[i] = (cxc*t[i] + cyc*cc[i])*idnc;
    float n2nc = fmaxf((cxc*cxc*x2c + 2.f*cxc*cyc*xyc + cyc*cyc*y2c)*idnc*idnc, 0.f);
    float nnc = sqrtf(n2nc + 1e-15f);
    if(nnc > PMF){
      float sc = __fdividef(PMF, nnc);
      #pragma unroll
      for(int i=0;i<4;i++) nc[i] *= sc;
      nnc = PMF;
    }
    float lt[4];
    {
      float sc = __fdividef(fatanh(nnc), nnc);
      #pragma unroll
      for(int i=0;i<4;i++) lt[i] = ftanh(nc[i]*sc);
    }
    float nlt = sqrtf(wdot<4>(lt,lt)+1e-15f);
    float nh[4];
    pwmulp_k(op, lt, nlt, nh);
    st4(out + 0*NN*128 + b, nh);
    st4(out + 1*NN*128 + b, nc);
  }

  // ---- Sphere
  {
    float z[12], io[12];
    #pragma unroll
    for(int c=0;c<3;c++){ ld4(z+4*c, g_Z2 + b3 + 128*c); ld4(io+4*c, iou2 + b3 + 128*c); }
    float nz = sqrtf(wdot<12>(z,z)+1e-15f);
    float mz = ftan(nz);
    {
      float sc = __fdividef(mz, nz);
      #pragma unroll
      for(int i=0;i<12;i++) z[i] *= sc;
    }
    float x2 = wdot<12>(io,io);
    float xy = wdot<12>(io,z);
    float y2 = mz*mz;
    float cx = 1.f-2.f*xy-y2, cy = 1.f+x2;
    float idn = __fdividef(1.f, safe_den(1.f-2.f*xy+x2*y2));
    float ni[12];
    #pragma unroll
    for(int i=0;i<12;i++) ni[i] = (cx*io[i] + cy*z[i])*idn;
    float ip[4], op[4], up[4];
    {
      float n0 = sqrtf(wdot<4>(ni,ni)+1e-15f);
      float s0 = __fdividef(atanf(n0), n0);
      float n1 = sqrtf(wdot<4>(ni+4,ni+4)+1e-15f);
      float s1 = __fdividef(atanf(n1), n1);
      float n2 = sqrtf(wdot<4>(ni+8,ni+8)+1e-15f);
      float s2 = __fdividef(atanf(n2), n2);
      #pragma unroll
      for(int i=0;i<4;i++){
        ip[i] = fsig(ni[i]*s0);
        op[i] = fsig(ni[4+i]*s1);
        up[i] = ftanh(ni[8+i]*s2);
      }
    }
    float nup = sqrtf(wdot<4>(up,up)+1e-15f);
    float t[4];
    float mt = pwmuls_k(ip, up, nup, t);
    float cc[4]; ld4(cc, g_c2o+b);
    float y2c = g_n2c2o[nd];
    float xys = 0.f;
    #pragma unroll
    for(int i=0;i<4;i++) xys += t[i]*cc[i];
    float xyc = wred(xys);
    float x2c = mt*mt;
    float cxc = 1.f-2.f*xyc-y2c, cyc = 1.f+x2c;
    float idnc = __fdividef(1.f, safe_den(1.f-2.f*xyc+x2c*y2c));
    float nc[4];
    #pragma unroll
    for(int i=0;i<4;i++) nc[i] = (cxc*t[i] + cyc*cc[i])*idnc;
    float n2nc = fmaxf((cxc*cxc*x2c + 2.f*cxc*cyc*xyc + cyc*cyc*y2c)*idnc*idnc, 0.f);
    float nnc = sqrtf(n2nc + 1e-15f);
    float lt[4];
    {
      float sc = __fdividef(atanf(nnc), nnc);
      #pragma unroll
      for(int i=0;i<4;i++) lt[i] = ftanh(nc[i]*sc);
    }
    float nlt = sqrtf(wdot<4>(lt,lt)+1e-15f);
    float nh[4];
    pwmuls_k(op, lt, nlt, nh);
    st4(out + 2*NN*128 + b, nh);
    st4(out + 3*NN*128 + b, nc);
  }

  // ---- Euclid
  {
    float z[12], io[12];
    #pragma unroll
    for(int c=0;c<3;c++){ ld4(z+4*c, g_Z3 + b3 + 128*c); ld4(io+4*c, iou3 + b3 + 128*c); }
    float cc[4]; ld4(cc, g_c3o+b);
    float nc[4], nh[4];
    #pragma unroll
    for(int i=0;i<4;i++){
      float ip = fsig(io[i]   + z[i]);
      float op = fsig(io[4+i] + z[4+i]);
      float up = ftanh(io[8+i] + z[8+i]);
      nc[i] = ip*up + cc[i];
      nh[i] = op*ftanh(nc[i]);
    }
    st4(out + 4*NN*128 + b, nh);
    st4(out + 5*NN*128 + b, nc);
  }
}

// ----------------------------- launch -----------------------------
extern "C" void kernel_launch(void* const* d_in, const int* in_sizes, int n_in,
                              void* d_out, int out_size){
  const float* x     = (const float*)d_in[0];
  const float* h1    = (const float*)d_in[1];
  const float* c1    = (const float*)d_in[2];
  const float* h2    = (const float*)d_in[3];
  const float* c2    = (const float*)d_in[4];
  const float* h3    = (const float*)d_in[5];
  const float* c3    = (const float*)d_in[6];
  const float* del_t = (const float*)d_in[7];
  const float* iou1  = (const float*)d_in[8];
  const float* iou2  = (const float*)d_in[9];
  const float* iou3  = (const float*)d_in[10];
  const float* Wq_w  = (const float*)d_in[11];
  const float* Wq_b  = (const float*)d_in[12];
  const float* Wc_w  = (const float*)d_in[13];
  const float* Wc_b  = (const float*)d_in[14];
  const float* Uf_w  = (const float*)d_in[15];
  const float* Uf_b  = (const float*)d_in[16];
  const float* Up_w  = (const float*)d_in[17];
  const float* Up_b  = (const float*)d_in[18];
  const float* Uiou_w= (const float*)d_in[19];
  const float* Uiou_b= (const float*)d_in[20];
  const float* dptr  = (const float*)d_in[21];
  const int*   nbr   = (const int*)d_in[22];
  float* out = (float*)d_out;

  cudaFuncSetAttribute(k_gemm1, cudaFuncAttributeMaxDynamicSharedMemorySize, GSMEM);
  cudaFuncSetAttribute(k_gemm2, cudaFuncAttributeMaxDynamicSharedMemorySize, GSMEM);

  k_prep<<<NN/8 + 224, 256>>>(h1, h2, c1, c2, x, h3, c3, Wq_w, Wc_w, Uf_w, Up_w, Uiou_w);
  k_gemm1<<<dim3(NN/64, 1, 10), 256, GSMEM>>>(Wq_b, Wc_b, Uf_b, Up_b);
  k_node<<<dim3(NN/8, 2), 256>>>(h1, h2, h3, c1, c2, c3, del_t, dptr);
  k_attn<<<NN/8, 256>>>(nbr);
  k_gemm2<<<dim3(NN/64, 3, 3), 256, GSMEM>>>(Uiou_b);
  k_final<<<NN/8, 256>>>(iou1, iou2, iou3, out);
}